// round 1
// baseline (speedup 1.0000x reference)
#include <cuda_runtime.h>
#include <math.h>

#define DEPTHN 12
#define BATCH 128
#define NTOK 197
#define NSP 196
#define CDIM 384
#define NHEAD 6
#define HDIM 64
#define MROWS (BATCH*NTOK)      /* 25216 */
#define FFDIM 1536
#define QKVDIM 1152

/* ---------------- scratch (device globals; no allocation allowed) -------- */
__device__ float g_x   [MROWS*CDIM];
__device__ float g_h   [MROWS*CDIM];
__device__ float g_qkv [MROWS*QKVDIM];
__device__ float g_attn[(long long)BATCH*NHEAD*NTOK*NTOK];
__device__ float g_ao  [MROWS*CDIM];
__device__ float g_ffn [MROWS*FFDIM];
__device__ float g_pol [BATCH*NTOK];
__device__ float g_ph  [BATCH*NSP*NHEAD*HDIM];
__device__ float g_glob[BATCH*NHEAD*32];
__device__ float g_den [BATCH];

__device__ __forceinline__ float gelu_f(float x) {
    return 0.5f * x * (1.0f + erff(x * 0.70710678118654752440f));
}

/* ---------------- block reductions --------------------------------------- */
__device__ __forceinline__ float blockReduceSum(float v, float* sh) {
    int tid = threadIdx.x, lane = tid & 31, w = tid >> 5;
    #pragma unroll
    for (int o = 16; o; o >>= 1) v += __shfl_xor_sync(0xffffffffu, v, o);
    if (lane == 0) sh[w] = v;
    __syncthreads();
    int nw = (blockDim.x + 31) >> 5;
    v = (tid < nw) ? sh[tid] : 0.f;
    if (w == 0) {
        #pragma unroll
        for (int o = 16; o; o >>= 1) v += __shfl_xor_sync(0xffffffffu, v, o);
        if (lane == 0) sh[0] = v;
    }
    __syncthreads();
    float r = sh[0];
    __syncthreads();
    return r;
}

__device__ __forceinline__ float blockReduceMax(float v, float* sh) {
    int tid = threadIdx.x, lane = tid & 31, w = tid >> 5;
    #pragma unroll
    for (int o = 16; o; o >>= 1) v = fmaxf(v, __shfl_xor_sync(0xffffffffu, v, o));
    if (lane == 0) sh[w] = v;
    __syncthreads();
    int nw = (blockDim.x + 31) >> 5;
    v = (tid < nw) ? sh[tid] : -1e30f;
    if (w == 0) {
        #pragma unroll
        for (int o = 16; o; o >>= 1) v = fmaxf(v, __shfl_xor_sync(0xffffffffu, v, o));
        if (lane == 0) sh[0] = v;
    }
    __syncthreads();
    float r = sh[0];
    __syncthreads();
    return r;
}

/* ---------------- generic tiled GEMM -------------------------------------
 * C[m,n] = alpha * sum_k A[m,k] * B(n,k)   (+bias[n]) (+epilogue)
 * BT=true : B is [N,K] row-major (B[n*ldb+k])  — "NT"
 * BT=false: B is [K,N] row-major (B[k*ldb+n])  — "NN"
 * EPI: 0 none, 1 gelu, 2 residual add (R, same layout as C)
 * Batched over blockIdx.z = zb*Hdim + zh with independent strides.
 */
#define GBM 128
#define GBN 128
#define GBK 8
#define GTM 8
#define GTN 8

template<bool BT, int EPI>
__global__ void __launch_bounds__(256)
gemm_k(const float* __restrict__ A, const float* __restrict__ B,
       const float* __restrict__ bias, const float* __restrict__ R,
       float* __restrict__ C,
       int M, int N, int K, int lda, int ldb, int ldc, float alpha,
       long long sAb, long long sAh, long long sBb, long long sBh,
       long long sCb, long long sCh, int Hdim)
{
    __shared__ float As[GBK][GBM];
    __shared__ float Bs[GBK][GBN];

    int z = blockIdx.z;
    int zb = z / Hdim, zh = z % Hdim;
    A += zb * sAb + zh * sAh;
    B += zb * sBb + zh * sBh;
    C += zb * sCb + zh * sCh;
    if (EPI == 2) R += zb * sCb + zh * sCh;

    int tid  = threadIdx.x;
    int brow = blockIdx.y * GBM;
    int bcol = blockIdx.x * GBN;
    int trow = (tid >> 4) * GTM;
    int tcol = (tid & 15) * GTN;

    float acc[GTM][GTN];
    #pragma unroll
    for (int i = 0; i < GTM; i++)
        #pragma unroll
        for (int j = 0; j < GTN; j++) acc[i][j] = 0.f;

    int ar = tid >> 1;
    int ak = (tid & 1) * 4;

    for (int k0 = 0; k0 < K; k0 += GBK) {
        /* load A tile (BM x BK), transposed into As[k][m] */
        {
            int m = brow + ar;
            #pragma unroll
            for (int i = 0; i < 4; i++) {
                int kk = k0 + ak + i;
                As[ak + i][ar] = (m < M && kk < K) ? A[(long long)m * lda + kk] : 0.f;
            }
        }
        if (BT) {
            int bn = tid >> 1;
            int bk = (tid & 1) * 4;
            int n = bcol + bn;
            #pragma unroll
            for (int i = 0; i < 4; i++) {
                int kk = k0 + bk + i;
                Bs[bk + i][bn] = (n < N && kk < K) ? B[(long long)n * ldb + kk] : 0.f;
            }
        } else {
            int bk = tid >> 5;
            int bn = (tid & 31) * 4;
            int kk = k0 + bk;
            #pragma unroll
            for (int i = 0; i < 4; i++) {
                int n = bcol + bn + i;
                Bs[bk][bn + i] = (n < N && kk < K) ? B[(long long)kk * ldb + n] : 0.f;
            }
        }
        __syncthreads();

        #pragma unroll
        for (int kk = 0; kk < GBK; kk++) {
            float ra[GTM], rb[GTN];
            #pragma unroll
            for (int i = 0; i < GTM; i++) ra[i] = As[kk][trow + i];
            #pragma unroll
            for (int j = 0; j < GTN; j++) rb[j] = Bs[kk][tcol + j];
            #pragma unroll
            for (int i = 0; i < GTM; i++)
                #pragma unroll
                for (int j = 0; j < GTN; j++)
                    acc[i][j] += ra[i] * rb[j];
        }
        __syncthreads();
    }

    #pragma unroll
    for (int i = 0; i < GTM; i++) {
        int m = brow + trow + i;
        if (m >= M) continue;
        #pragma unroll
        for (int j = 0; j < GTN; j++) {
            int n = bcol + tcol + j;
            if (n >= N) continue;
            float v = alpha * acc[i][j];
            if (bias) v += bias[n];
            if (EPI == 1)      v = gelu_f(v);
            else if (EPI == 2) v += R[(long long)m * ldc + n];
            C[(long long)m * ldc + n] = v;
        }
    }
}

/* ---------------- LayerNorm over C=384 ----------------------------------- */
__global__ void ln_k(const float* __restrict__ x, const float* __restrict__ w,
                     const float* __restrict__ bb, float* __restrict__ out, float eps)
{
    __shared__ float sh[32];
    long long row = blockIdx.x;
    const float* xr = x + row * CDIM;
    int tid = threadIdx.x; /* 128 */
    float v0 = xr[tid], v1 = xr[tid + 128], v2 = xr[tid + 256];
    float s = blockReduceSum(v0 + v1 + v2, sh);
    float m = s * (1.f / 384.f);
    float d0 = v0 - m, d1 = v1 - m, d2 = v2 - m;
    float q = blockReduceSum(d0*d0 + d1*d1 + d2*d2, sh);
    float rs = rsqrtf(q * (1.f / 384.f) + eps);
    float* orow = out + row * CDIM;
    orow[tid]       = d0 * rs * w[tid]       + bb[tid];
    orow[tid + 128] = d1 * rs * w[tid + 128] + bb[tid + 128];
    orow[tid + 256] = d2 * rs * w[tid + 256] + bb[tid + 256];
}

/* ---------------- policy softmax over one score row ----------------------- */
__global__ void softmax_pol_k(float* __restrict__ attn, const float* __restrict__ pol)
{
    __shared__ float sh[32];
    __shared__ float rowv[NTOK];
    long long r = blockIdx.x;          /* (b*6+h)*197 + n */
    int n = (int)(r % NTOK);
    int b = (int)(r / ((long long)NHEAD * NTOK));
    float* row = attn + r * NTOK;
    const float* pb = pol + b * NTOK;
    int tid = threadIdx.x; /* 128 */

    float mx = -1e30f;
    for (int m = tid; m < NTOK; m += 128) { float v = row[m]; rowv[m] = v; mx = fmaxf(mx, v); }
    mx = blockReduceMax(mx, sh);

    float sum = 0.f;
    for (int m = tid; m < NTOK; m += 128) {
        float ap = (m == n) ? 1.0f : pb[m];
        float e = expf(rowv[m] - mx) * ap;
        rowv[m] = e;
        sum += e;
    }
    sum = blockReduceSum(sum, sh);
    float inv = 1.0f / sum;
    for (int m = tid; m < NTOK; m += 128) row[m] = rowv[m] * inv;
}

/* ---------------- init / final ------------------------------------------- */
__global__ void init_x_k(const float* __restrict__ xin, const float* __restrict__ cls,
                         const float* __restrict__ polin,
                         float* __restrict__ x, float* __restrict__ pol)
{
    long long idx = (long long)blockIdx.x * blockDim.x + threadIdx.x;
    long long total = (long long)MROWS * CDIM;
    if (idx < total) {
        int c  = (int)(idx % CDIM);
        int nn = (int)((idx / CDIM) % NTOK);
        int b  = (int)(idx / ((long long)CDIM * NTOK));
        float v;
        if (nn == 0) v = cls[b * CDIM + c];
        else         v = xin[((long long)b * CDIM + c) * NSP + (nn - 1)];
        x[idx] = v;
    }
    if (idx < BATCH * NTOK) pol[idx] = polin[idx];
}

__global__ void final_k(const float* __restrict__ x, float* __restrict__ out)
{
    long long idx = (long long)blockIdx.x * blockDim.x + threadIdx.x;
    const long long total_sp = (long long)BATCH * CDIM * NSP;
    if (idx < total_sp) {
        int hw = (int)(idx % NSP);
        int c  = (int)((idx / NSP) % CDIM);
        int b  = (int)(idx / ((long long)NSP * CDIM));
        out[idx] = x[((long long)(b * NTOK) + 1 + hw) * CDIM + c];
    } else if (idx < total_sp + (long long)BATCH * CDIM) {
        long long rr = idx - total_sp;
        int c = (int)(rr % CDIM);
        int b = (int)(rr / CDIM);
        out[idx] = x[((long long)b * NTOK) * CDIM + c];
    }
}

/* ---------------- predictor --------------------------------------------- */
__global__ void den_k(const float* __restrict__ pol, float* __restrict__ den)
{
    __shared__ float sh[32];
    int b = blockIdx.x;
    int tid = threadIdx.x; /* 256 */
    float v = (tid < NSP) ? pol[b * NTOK + 1 + tid] : 0.f;
    float s = blockReduceSum(v, sh);
    if (tid == 0) den[b] = s;
}

/* stage 1: per (b,n,head): LN(64, eps 1e-5) -> gelu(x @ Win^T + bin) */
__global__ void p1_k(const float* __restrict__ x,
                     const float* __restrict__ lnw, const float* __restrict__ lnb,
                     const float* __restrict__ Win, const float* __restrict__ bin,
                     float* __restrict__ ph)
{
    int bn = blockIdx.x;                 /* b*196+n */
    int b = bn / NSP, n = bn % NSP;
    int wid = threadIdx.x >> 5, lane = threadIdx.x & 31;  /* 6 warps */
    __shared__ float sh[NHEAD][HDIM];

    const float* xr = x + ((long long)(b * NTOK + 1 + n)) * CDIM + wid * HDIM;
    float v0 = xr[lane], v1 = xr[lane + 32];
    float s = v0 + v1;
    #pragma unroll
    for (int o = 16; o; o >>= 1) s += __shfl_xor_sync(0xffffffffu, s, o);
    float m = s * (1.f / 64.f);
    float d0 = v0 - m, d1 = v1 - m;
    float q = d0*d0 + d1*d1;
    #pragma unroll
    for (int o = 16; o; o >>= 1) q += __shfl_xor_sync(0xffffffffu, q, o);
    float rs = rsqrtf(q * (1.f / 64.f) + 1e-5f);
    sh[wid][lane]      = d0 * rs * lnw[lane]      + lnb[lane];
    sh[wid][lane + 32] = d1 * rs * lnw[lane + 32] + lnb[lane + 32];
    __syncwarp();

    float a0 = bin[lane], a1 = bin[lane + 32];
    const float* w0 = Win + lane * 64;
    const float* w1 = Win + (lane + 32) * 64;
    #pragma unroll 8
    for (int e = 0; e < 64; e++) {
        float he = sh[wid][e];
        a0 += w0[e] * he;
        a1 += w1[e] * he;
    }
    float* o = ph + ((long long)bn * NHEAD + wid) * HDIM;
    o[lane]      = gelu_f(a0);
    o[lane + 32] = gelu_f(a1);
}

/* stage 2: global pooling of h[...,32:] weighted by policy */
__global__ void p2_k(const float* __restrict__ ph, const float* __restrict__ pol,
                     const float* __restrict__ den, float* __restrict__ glob)
{
    int bh = blockIdx.x;                 /* b*6+h */
    int b = bh / NHEAD, h = bh % NHEAD;
    int tid = threadIdx.x;               /* 256 */
    int d = tid & 31, seg = tid >> 5;    /* 8 segs */
    float s = 0.f;
    for (int n = seg; n < NSP; n += 8)
        s += ph[(((long long)(b * NSP + n)) * NHEAD + h) * HDIM + 32 + d]
             * pol[b * NTOK + 1 + n];
    __shared__ float sh[8][32];
    sh[seg][d] = s;
    __syncthreads();
    if (seg == 0) {
        float t = 0.f;
        #pragma unroll
        for (int k = 0; k < 8; k++) t += sh[k][d];
        glob[(b * NHEAD + h) * 32 + d] = t / den[b];
    }
}

/* stage 3: tiny MLP head + log-softmax mean + gumbel hard decision */
__global__ void p3_k(const float* __restrict__ ph, const float* __restrict__ glob,
                     const float* __restrict__ W1, const float* __restrict__ b1,
                     const float* __restrict__ W2, const float* __restrict__ b2,
                     const float* __restrict__ W3, const float* __restrict__ b3,
                     const float* __restrict__ gum, float* __restrict__ pol)
{
    int bn = blockIdx.x;
    int b = bn / NSP, n = bn % NSP;
    int wid = threadIdx.x >> 5, lane = threadIdx.x & 31;   /* 6 warps */
    __shared__ float h2[NHEAD][64];
    __shared__ float o1[NHEAD][32];
    __shared__ float o2[NHEAD][16];
    __shared__ float zz[NHEAD][2];

    const float* hin = ph + ((long long)bn * NHEAD + wid) * HDIM;
    h2[wid][lane]      = hin[lane];
    h2[wid][32 + lane] = glob[(b * NHEAD + wid) * 32 + lane];
    __syncwarp();
    {
        float a = b1[lane];
        const float* wr = W1 + lane * 64;
        #pragma unroll 8
        for (int e = 0; e < 64; e++) a += wr[e] * h2[wid][e];
        o1[wid][lane] = gelu_f(a);
    }
    __syncwarp();
    if (lane < 16) {
        float a = b2[lane];
        const float* wr = W2 + lane * 32;
        #pragma unroll 8
        for (int e = 0; e < 32; e++) a += wr[e] * o1[wid][e];
        o2[wid][lane] = gelu_f(a);
    }
    __syncwarp();
    if (lane < 2) {
        float a = b3[lane];
        const float* wr = W3 + lane * 16;
        #pragma unroll
        for (int e = 0; e < 16; e++) a += wr[e] * o2[wid][e];
        zz[wid][lane] = a;
    }
    __syncthreads();
    if (threadIdx.x == 0) {
        float s0 = 0.f, s1 = 0.f;
        #pragma unroll
        for (int h = 0; h < NHEAD; h++) {
            float z0 = zz[h][0], z1 = zz[h][1];
            float mx = fmaxf(z0, z1);
            float lse = mx + logf(expf(z0 - mx) + expf(z1 - mx));
            s0 += z0 - lse;
            s1 += z1 - lse;
        }
        s0 *= (1.f / 6.f); s1 *= (1.f / 6.f);
        float u0 = gum[((long long)b * NSP + n) * 2 + 0];
        float u1 = gum[((long long)b * NSP + n) * 2 + 1];
        float g0 = -logf(-logf(u0 + 1e-10f) + 1e-10f);
        float g1 = -logf(-logf(u1 + 1e-10f) + 1e-10f);
        int idx = b * NTOK + 1 + n;
        float keep = (s0 + g0 >= s1 + g1) ? pol[idx] : 0.f;
        pol[idx] = keep;
    }
}

/* ---------------- host-side launch helpers ------------------------------- */
static void launch_gemm(bool bt, int epi, dim3 grd,
                        const float* A, const float* B, const float* bias, const float* R,
                        float* C, int M, int N, int K, int lda, int ldb, int ldc, float alpha,
                        long long sAb, long long sAh, long long sBb, long long sBh,
                        long long sCb, long long sCh, int Hdim)
{
#define GEMM_ARGS A,B,bias,R,C,M,N,K,lda,ldb,ldc,alpha,sAb,sAh,sBb,sBh,sCb,sCh,Hdim
    if (bt) {
        if (epi == 0)      gemm_k<true, 0><<<grd, 256>>>(GEMM_ARGS);
        else if (epi == 1) gemm_k<true, 1><<<grd, 256>>>(GEMM_ARGS);
        else               gemm_k<true, 2><<<grd, 256>>>(GEMM_ARGS);
    } else {
        if (epi == 0)      gemm_k<false, 0><<<grd, 256>>>(GEMM_ARGS);
        else if (epi == 1) gemm_k<false, 1><<<grd, 256>>>(GEMM_ARGS);
        else               gemm_k<false, 2><<<grd, 256>>>(GEMM_ARGS);
    }
#undef GEMM_ARGS
}

extern "C" void kernel_launch(void* const* d_in, const int* in_sizes, int n_in,
                              void* d_out, int out_size)
{
    const float* in_x     = (const float*)d_in[0];
    const float* in_cls   = (const float*)d_in[1];
    const float* in_pol   = (const float*)d_in[2];
    const float* in_gum   = (const float*)d_in[3];
    const float* ln1_w    = (const float*)d_in[4];
    const float* ln1_b    = (const float*)d_in[5];
    const float* qkv_w    = (const float*)d_in[6];
    const float* qkv_b    = (const float*)d_in[7];
    const float* proj_w   = (const float*)d_in[8];
    const float* proj_b   = (const float*)d_in[9];
    const float* ln2_w    = (const float*)d_in[10];
    const float* ln2_b    = (const float*)d_in[11];
    const float* fc1_w    = (const float*)d_in[12];
    const float* fc1_b    = (const float*)d_in[13];
    const float* fc2_w    = (const float*)d_in[14];
    const float* fc2_b    = (const float*)d_in[15];
    const float* p_ln_w   = (const float*)d_in[16];
    const float* p_ln_b   = (const float*)d_in[17];
    const float* p_in_w   = (const float*)d_in[18];
    const float* p_in_b   = (const float*)d_in[19];
    const float* p_o1_w   = (const float*)d_in[20];
    const float* p_o1_b   = (const float*)d_in[21];
    const float* p_o2_w   = (const float*)d_in[22];
    const float* p_o2_b   = (const float*)d_in[23];
    const float* p_o3_w   = (const float*)d_in[24];
    const float* p_o3_b   = (const float*)d_in[25];

    float *px, *phb, *pqkv, *pattn, *pao, *pffn, *ppol, *pph, *pglob, *pden;
    cudaGetSymbolAddress((void**)&px,    g_x);
    cudaGetSymbolAddress((void**)&phb,   g_h);
    cudaGetSymbolAddress((void**)&pqkv,  g_qkv);
    cudaGetSymbolAddress((void**)&pattn, g_attn);
    cudaGetSymbolAddress((void**)&pao,   g_ao);
    cudaGetSymbolAddress((void**)&pffn,  g_ffn);
    cudaGetSymbolAddress((void**)&ppol,  g_pol);
    cudaGetSymbolAddress((void**)&pph,   g_ph);
    cudaGetSymbolAddress((void**)&pglob, g_glob);
    cudaGetSymbolAddress((void**)&pden,  g_den);

    /* init tokens + policy */
    {
        long long total = (long long)MROWS * CDIM;
        int blocks = (int)((total + 255) / 256);
        init_x_k<<<blocks, 256>>>(in_x, in_cls, in_pol, px, ppol);
    }

    int pc = 0;
    for (int i = 0; i < DEPTHN; i++) {
        if (i == 3 || i == 6 || i == 9) {
            den_k<<<BATCH, 256>>>(ppol, pden);
            p1_k<<<BATCH * NSP, 192>>>(px,
                p_ln_w + pc * HDIM, p_ln_b + pc * HDIM,
                p_in_w + pc * HDIM * HDIM, p_in_b + pc * HDIM, pph);
            p2_k<<<BATCH * NHEAD, 256>>>(pph, ppol, pden, pglob);
            p3_k<<<BATCH * NSP, 192>>>(pph, pglob,
                p_o1_w + pc * 32 * 64, p_o1_b + pc * 32,
                p_o2_w + pc * 16 * 32, p_o2_b + pc * 16,
                p_o3_w + pc * 2 * 16,  p_o3_b + pc * 2,
                in_gum + (long long)pc * BATCH * NSP * 2, ppol);
            pc++;
        }

        /* ---- attention sub-block ---- */
        ln_k<<<MROWS, 128>>>(px, ln1_w + i * CDIM, ln1_b + i * CDIM, phb, 1e-6f);

        /* qkv: [25216,384] @ [1152,384]^T + b */
        launch_gemm(true, 0, dim3(QKVDIM / GBN, MROWS / GBM, 1),
                    phb, qkv_w + (long long)i * QKVDIM * CDIM, qkv_b + i * QKVDIM, nullptr,
                    pqkv, MROWS, QKVDIM, CDIM, CDIM, CDIM, QKVDIM, 1.0f,
                    0, 0, 0, 0, 0, 0, 1);

        /* scores: per (b,h): Q[197,64] @ K[197,64]^T * 0.125 */
        launch_gemm(true, 0, dim3(2, 2, BATCH * NHEAD),
                    pqkv, pqkv + CDIM, nullptr, nullptr, pattn,
                    NTOK, NTOK, HDIM, QKVDIM, QKVDIM, NTOK, 0.125f,
                    (long long)NTOK * QKVDIM, HDIM,
                    (long long)NTOK * QKVDIM, HDIM,
                    (long long)NHEAD * NTOK * NTOK, (long long)NTOK * NTOK, NHEAD);

        softmax_pol_k<<<BATCH * NHEAD * NTOK, 128>>>(pattn, ppol);

        /* O = A @ V : per (b,h): [197,197] @ [197,64] (NN) -> [B,N,H,HD] layout */
        launch_gemm(false, 0, dim3(1, 2, BATCH * NHEAD),
                    pattn, pqkv + 2 * CDIM, nullptr, nullptr, pao,
                    NTOK, HDIM, NTOK, NTOK, QKVDIM, CDIM, 1.0f,
                    (long long)NHEAD * NTOK * NTOK, (long long)NTOK * NTOK,
                    (long long)NTOK * QKVDIM, HDIM,
                    (long long)NTOK * CDIM, HDIM, NHEAD);

        /* proj + residual into x */
        launch_gemm(true, 2, dim3(CDIM / GBN, MROWS / GBM, 1),
                    pao, proj_w + (long long)i * CDIM * CDIM, proj_b + i * CDIM, px,
                    px, MROWS, CDIM, CDIM, CDIM, CDIM, CDIM, 1.0f,
                    0, 0, 0, 0, 0, 0, 1);

        /* ---- MLP sub-block ---- */
        ln_k<<<MROWS, 128>>>(px, ln2_w + i * CDIM, ln2_b + i * CDIM, phb, 1e-6f);

        launch_gemm(true, 1, dim3(FFDIM / GBN, MROWS / GBM, 1),
                    phb, fc1_w + (long long)i * FFDIM * CDIM, fc1_b + i * FFDIM, nullptr,
                    pffn, MROWS, FFDIM, CDIM, CDIM, CDIM, FFDIM, 1.0f,
                    0, 0, 0, 0, 0, 0, 1);

        launch_gemm(true, 2, dim3(CDIM / GBN, MROWS / GBM, 1),
                    pffn, fc2_w + (long long)i * CDIM * FFDIM, fc2_b + i * CDIM, px,
                    px, MROWS, CDIM, FFDIM, FFDIM, FFDIM, CDIM, 1.0f,
                    0, 0, 0, 0, 0, 0, 1);
    }

    /* final output: sp (B,C,14,14) then cls (B,1,C) */
    {
        long long total = (long long)BATCH * CDIM * NSP + (long long)BATCH * CDIM;
        int blocks = (int)((total + 255) / 256);
        final_k<<<blocks, 256>>>(px, (float*)d_out);
    }
}

// round 3
// speedup vs baseline: 1.9970x; 1.9970x over previous
#include <cuda_runtime.h>
#include <math.h>
#include <stdint.h>

#define DEPTHN 12
#define BATCH 128
#define NTOK 197
#define NSP 196
#define CDIM 384
#define NHEAD 6
#define HDIM 64
#define MROWS (BATCH*NTOK)      /* 25216 */
#define FFDIM 1536
#define QKVDIM 1152

/* ---------------- scratch (device globals; no allocation allowed) -------- */
__device__ float g_x   [MROWS*CDIM];
__device__ float g_h   [MROWS*CDIM];
__device__ float g_qkv [MROWS*QKVDIM];
__device__ float g_attn[(long long)BATCH*NHEAD*NTOK*NTOK];
__device__ float g_ao  [MROWS*CDIM];
__device__ float g_ffn [MROWS*FFDIM];
__device__ float g_pol [BATCH*NTOK];
__device__ float g_ph  [BATCH*NSP*NHEAD*HDIM];
__device__ float g_glob[BATCH*NHEAD*32];
__device__ float g_den [BATCH];

__device__ __forceinline__ float gelu_f(float x) {
    return 0.5f * x * (1.0f + erff(x * 0.70710678118654752440f));
}

__device__ __forceinline__ uint32_t f2tf32(float f) {
    uint32_t u;
    asm("cvt.rna.tf32.f32 %0, %1;" : "=r"(u) : "f"(f));
    return u;
}

__device__ __forceinline__ void mma_tf32_16n8k8(
    float& d0, float& d1, float& d2, float& d3,
    uint32_t a0, uint32_t a1, uint32_t a2, uint32_t a3,
    uint32_t b0, uint32_t b1)
{
    asm volatile(
        "mma.sync.aligned.m16n8k8.row.col.f32.tf32.tf32.f32 "
        "{%0,%1,%2,%3}, {%4,%5,%6,%7}, {%8,%9}, {%0,%1,%2,%3};"
        : "+f"(d0), "+f"(d1), "+f"(d2), "+f"(d3)
        : "r"(a0), "r"(a1), "r"(a2), "r"(a3), "r"(b0), "r"(b1));
}

/* ================= HMMA tf32 dense GEMM ==================================
 * C[m,n] = sum_k A[m,k]*B[n,k] + bias[n]   (EPI: 0 none, 1 gelu, 2 +R)
 * A: [M, lda] row-major, B: [N, ldb] row-major (NT). M%128==0, N%128==0, K%32==0.
 * 256 threads = 8 warps (2 x 4 warp grid), warp tile 64x32, CTA tile 128x128x32.
 */
#define SPAD 36

template<int EPI>
__global__ void __launch_bounds__(256, 2)
tcgemm_k(const float* __restrict__ A, const float* __restrict__ B,
         const float* __restrict__ bias, const float* __restrict__ R,
         float* __restrict__ C, int K, int lda, int ldb, int ldc)
{
    __shared__ uint32_t As[128][SPAD];
    __shared__ uint32_t Bs[128][SPAD];

    const int tid  = threadIdx.x;
    const int wid  = tid >> 5, lane = tid & 31;
    const int lane4 = lane >> 2, lanek = lane & 3;
    const int warpM = wid & 1, warpN = wid >> 1;
    const int m0 = blockIdx.y * 128, n0 = blockIdx.x * 128;

    float acc[4][4][4];
    #pragma unroll
    for (int i = 0; i < 4; i++)
        #pragma unroll
        for (int j = 0; j < 4; j++)
            #pragma unroll
            for (int r = 0; r < 4; r++) acc[i][j][r] = 0.f;

    const int lrow = tid >> 3;        /* 0..31 step rows per 256-thread pass */
    const int lkq  = tid & 7;         /* float4 slot in k (8 per 32-k row)   */

    for (int k0 = 0; k0 < K; k0 += 32) {
        /* load A/B 128x32 tiles, convert to tf32, store padded */
        #pragma unroll
        for (int i = 0; i < 4; i++) {
            int row = lrow + i * 32;
            float4 va = *(const float4*)(A + (size_t)(m0 + row) * lda + k0 + lkq * 4);
            float4 vb = *(const float4*)(B + (size_t)(n0 + row) * ldb + k0 + lkq * 4);
            uint32_t* pa = &As[row][lkq * 4];
            uint32_t* pb = &Bs[row][lkq * 4];
            pa[0] = f2tf32(va.x); pa[1] = f2tf32(va.y);
            pa[2] = f2tf32(va.z); pa[3] = f2tf32(va.w);
            pb[0] = f2tf32(vb.x); pb[1] = f2tf32(vb.y);
            pb[2] = f2tf32(vb.z); pb[3] = f2tf32(vb.w);
        }
        __syncthreads();

        #pragma unroll
        for (int ks = 0; ks < 4; ks++) {
            const int kk = ks * 8 + lanek;
            uint32_t a[4][4], b[4][2];
            #pragma unroll
            for (int mf = 0; mf < 4; mf++) {
                int rb = warpM * 64 + mf * 16 + lane4;
                a[mf][0] = As[rb][kk];
                a[mf][1] = As[rb + 8][kk];
                a[mf][2] = As[rb][kk + 4];
                a[mf][3] = As[rb + 8][kk + 4];
            }
            #pragma unroll
            for (int nf = 0; nf < 4; nf++) {
                int nb = warpN * 32 + nf * 8 + lane4;
                b[nf][0] = Bs[nb][kk];
                b[nf][1] = Bs[nb][kk + 4];
            }
            #pragma unroll
            for (int mf = 0; mf < 4; mf++)
                #pragma unroll
                for (int nf = 0; nf < 4; nf++)
                    mma_tf32_16n8k8(acc[mf][nf][0], acc[mf][nf][1],
                                    acc[mf][nf][2], acc[mf][nf][3],
                                    a[mf][0], a[mf][1], a[mf][2], a[mf][3],
                                    b[nf][0], b[nf][1]);
        }
        __syncthreads();
    }

    /* epilogue: registers -> global, bias + EPI */
    #pragma unroll
    for (int mf = 0; mf < 4; mf++) {
        int m = m0 + warpM * 64 + mf * 16 + lane4;
        #pragma unroll
        for (int nf = 0; nf < 4; nf++) {
            int n = n0 + warpN * 32 + nf * 8 + lanek * 2;
            float bz0 = bias ? __ldg(bias + n)     : 0.f;
            float bz1 = bias ? __ldg(bias + n + 1) : 0.f;
            size_t gi0 = (size_t)m * ldc + n;
            size_t gi1 = (size_t)(m + 8) * ldc + n;
            float v0 = acc[mf][nf][0] + bz0;
            float v1 = acc[mf][nf][1] + bz1;
            float v2 = acc[mf][nf][2] + bz0;
            float v3 = acc[mf][nf][3] + bz1;
            if (EPI == 1) {
                v0 = gelu_f(v0); v1 = gelu_f(v1);
                v2 = gelu_f(v2); v3 = gelu_f(v3);
            } else if (EPI == 2) {
                v0 += R[gi0]; v1 += R[gi0 + 1];
                v2 += R[gi1]; v3 += R[gi1 + 1];
            }
            *(float2*)(C + gi0) = make_float2(v0, v1);
            *(float2*)(C + gi1) = make_float2(v2, v3);
        }
    }
}

/* ---------------- block reductions --------------------------------------- */
__device__ __forceinline__ float blockReduceSum(float v, float* sh) {
    int tid = threadIdx.x, lane = tid & 31, w = tid >> 5;
    #pragma unroll
    for (int o = 16; o; o >>= 1) v += __shfl_xor_sync(0xffffffffu, v, o);
    if (lane == 0) sh[w] = v;
    __syncthreads();
    int nw = (blockDim.x + 31) >> 5;
    v = (tid < nw) ? sh[tid] : 0.f;
    if (w == 0) {
        #pragma unroll
        for (int o = 16; o; o >>= 1) v += __shfl_xor_sync(0xffffffffu, v, o);
        if (lane == 0) sh[0] = v;
    }
    __syncthreads();
    float r = sh[0];
    __syncthreads();
    return r;
}

__device__ __forceinline__ float blockReduceMax(float v, float* sh) {
    int tid = threadIdx.x, lane = tid & 31, w = tid >> 5;
    #pragma unroll
    for (int o = 16; o; o >>= 1) v = fmaxf(v, __shfl_xor_sync(0xffffffffu, v, o));
    if (lane == 0) sh[w] = v;
    __syncthreads();
    int nw = (blockDim.x + 31) >> 5;
    v = (tid < nw) ? sh[tid] : -1e30f;
    if (w == 0) {
        #pragma unroll
        for (int o = 16; o; o >>= 1) v = fmaxf(v, __shfl_xor_sync(0xffffffffu, v, o));
        if (lane == 0) sh[0] = v;
    }
    __syncthreads();
    float r = sh[0];
    __syncthreads();
    return r;
}

/* ---------------- batched attention GEMM (z decomposed into (b,h)) ------- */
#define GBM 128
#define GBN 128
#define GBK 8
#define GTM 8
#define GTN 8

template<bool BT>
__global__ void __launch_bounds__(256)
gemm_k(const float* __restrict__ A, const float* __restrict__ B,
       float* __restrict__ C,
       int M, int N, int K, int lda, int ldb, int ldc, float alpha,
       long long sAb, long long sAh, long long sBb, long long sBh,
       long long sCb, long long sCh)
{
    __shared__ float As[GBK][GBM];
    __shared__ float Bs[GBK][GBN];

    int z = blockIdx.z;
    int zb = z / NHEAD, zh = z % NHEAD;
    A += zb * sAb + zh * sAh;
    B += zb * sBb + zh * sBh;
    C += zb * sCb + zh * sCh;

    int tid  = threadIdx.x;
    int brow = blockIdx.y * GBM;
    int bcol = blockIdx.x * GBN;
    int trow = (tid >> 4) * GTM;
    int tcol = (tid & 15) * GTN;

    float acc[GTM][GTN];
    #pragma unroll
    for (int i = 0; i < GTM; i++)
        #pragma unroll
        for (int j = 0; j < GTN; j++) acc[i][j] = 0.f;

    int ar = tid >> 1;
    int ak = (tid & 1) * 4;

    for (int k0 = 0; k0 < K; k0 += GBK) {
        {
            int m = brow + ar;
            #pragma unroll
            for (int i = 0; i < 4; i++) {
                int kk = k0 + ak + i;
                As[ak + i][ar] = (m < M && kk < K) ? A[(long long)m * lda + kk] : 0.f;
            }
        }
        if (BT) {
            int bn = tid >> 1;
            int bk = (tid & 1) * 4;
            int n = bcol + bn;
            #pragma unroll
            for (int i = 0; i < 4; i++) {
                int kk = k0 + bk + i;
                Bs[bk + i][bn] = (n < N && kk < K) ? B[(long long)n * ldb + kk] : 0.f;
            }
        } else {
            int bk = tid >> 5;
            int bn = (tid & 31) * 4;
            int kk = k0 + bk;
            #pragma unroll
            for (int i = 0; i < 4; i++) {
                int n = bcol + bn + i;
                Bs[bk][bn + i] = (n < N && kk < K) ? B[(long long)kk * ldb + n] : 0.f;
            }
        }
        __syncthreads();

        #pragma unroll
        for (int kk = 0; kk < GBK; kk++) {
            float ra[GTM], rb[GTN];
            #pragma unroll
            for (int i = 0; i < GTM; i++) ra[i] = As[kk][trow + i];
            #pragma unroll
            for (int j = 0; j < GTN; j++) rb[j] = Bs[kk][tcol + j];
            #pragma unroll
            for (int i = 0; i < GTM; i++)
                #pragma unroll
                for (int j = 0; j < GTN; j++)
                    acc[i][j] += ra[i] * rb[j];
        }
        __syncthreads();
    }

    #pragma unroll
    for (int i = 0; i < GTM; i++) {
        int m = brow + trow + i;
        if (m >= M) continue;
        #pragma unroll
        for (int j = 0; j < GTN; j++) {
            int n = bcol + tcol + j;
            if (n >= N) continue;
            C[(long long)m * ldc + n] = alpha * acc[i][j];
        }
    }
}

/* ---------------- LayerNorm over C=384 ----------------------------------- */
__global__ void ln_k(const float* __restrict__ x, const float* __restrict__ w,
                     const float* __restrict__ bb, float* __restrict__ out, float eps)
{
    __shared__ float sh[32];
    long long row = blockIdx.x;
    const float* xr = x + row * CDIM;
    int tid = threadIdx.x; /* 128 */
    float v0 = xr[tid], v1 = xr[tid + 128], v2 = xr[tid + 256];
    float s = blockReduceSum(v0 + v1 + v2, sh);
    float m = s * (1.f / 384.f);
    float d0 = v0 - m, d1 = v1 - m, d2 = v2 - m;
    float q = blockReduceSum(d0*d0 + d1*d1 + d2*d2, sh);
    float rs = rsqrtf(q * (1.f / 384.f) + eps);
    float* orow = out + row * CDIM;
    orow[tid]       = d0 * rs * w[tid]       + bb[tid];
    orow[tid + 128] = d1 * rs * w[tid + 128] + bb[tid + 128];
    orow[tid + 256] = d2 * rs * w[tid + 256] + bb[tid + 256];
}

/* ---------------- policy softmax over one score row ----------------------- */
__global__ void softmax_pol_k(float* __restrict__ attn, const float* __restrict__ pol)
{
    __shared__ float sh[32];
    __shared__ float rowv[NTOK];
    long long r = blockIdx.x;
    int n = (int)(r % NTOK);
    int b = (int)(r / ((long long)NHEAD * NTOK));
    float* row = attn + r * NTOK;
    const float* pb = pol + b * NTOK;
    int tid = threadIdx.x; /* 128 */

    float mx = -1e30f;
    for (int m = tid; m < NTOK; m += 128) { float v = row[m]; rowv[m] = v; mx = fmaxf(mx, v); }
    mx = blockReduceMax(mx, sh);

    float sum = 0.f;
    for (int m = tid; m < NTOK; m += 128) {
        float ap = (m == n) ? 1.0f : pb[m];
        float e = expf(rowv[m] - mx) * ap;
        rowv[m] = e;
        sum += e;
    }
    sum = blockReduceSum(sum, sh);
    float inv = 1.0f / sum;
    for (int m = tid; m < NTOK; m += 128) row[m] = rowv[m] * inv;
}

/* ---------------- init / final ------------------------------------------- */
__global__ void init_x_k(const float* __restrict__ xin, const float* __restrict__ cls,
                         const float* __restrict__ polin,
                         float* __restrict__ x, float* __restrict__ pol)
{
    long long idx = (long long)blockIdx.x * blockDim.x + threadIdx.x;
    long long total = (long long)MROWS * CDIM;
    if (idx < total) {
        int c  = (int)(idx % CDIM);
        int nn = (int)((idx / CDIM) % NTOK);
        int b  = (int)(idx / ((long long)CDIM * NTOK));
        float v;
        if (nn == 0) v = cls[b * CDIM + c];
        else         v = xin[((long long)b * CDIM + c) * NSP + (nn - 1)];
        x[idx] = v;
    }
    if (idx < BATCH * NTOK) pol[idx] = polin[idx];
}

__global__ void final_k(const float* __restrict__ x, float* __restrict__ out)
{
    long long idx = (long long)blockIdx.x * blockDim.x + threadIdx.x;
    const long long total_sp = (long long)BATCH * CDIM * NSP;
    if (idx < total_sp) {
        int hw = (int)(idx % NSP);
        int c  = (int)((idx / NSP) % CDIM);
        int b  = (int)(idx / ((long long)NSP * CDIM));
        out[idx] = x[((long long)(b * NTOK) + 1 + hw) * CDIM + c];
    } else if (idx < total_sp + (long long)BATCH * CDIM) {
        long long rr = idx - total_sp;
        int c = (int)(rr % CDIM);
        int b = (int)(rr / CDIM);
        out[idx] = x[((long long)b * NTOK) * CDIM + c];
    }
}

/* ---------------- predictor --------------------------------------------- */
__global__ void den_k(const float* __restrict__ pol, float* __restrict__ den)
{
    __shared__ float sh[32];
    int b = blockIdx.x;
    int tid = threadIdx.x;
    float v = (tid < NSP) ? pol[b * NTOK + 1 + tid] : 0.f;
    float s = blockReduceSum(v, sh);
    if (tid == 0) den[b] = s;
}

__global__ void p1_k(const float* __restrict__ x,
                     const float* __restrict__ lnw, const float* __restrict__ lnb,
                     const float* __restrict__ Win, const float* __restrict__ bin,
                     float* __restrict__ ph)
{
    int bn = blockIdx.x;
    int b = bn / NSP, n = bn % NSP;
    int wid = threadIdx.x >> 5, lane = threadIdx.x & 31;
    __shared__ float sh[NHEAD][HDIM];

    const float* xr = x + ((long long)(b * NTOK + 1 + n)) * CDIM + wid * HDIM;
    float v0 = xr[lane], v1 = xr[lane + 32];
    float s = v0 + v1;
    #pragma unroll
    for (int o = 16; o; o >>= 1) s += __shfl_xor_sync(0xffffffffu, s, o);
    float m = s * (1.f / 64.f);
    float d0 = v0 - m, d1 = v1 - m;
    float q = d0*d0 + d1*d1;
    #pragma unroll
    for (int o = 16; o; o >>= 1) q += __shfl_xor_sync(0xffffffffu, q, o);
    float rs = rsqrtf(q * (1.f / 64.f) + 1e-5f);
    sh[wid][lane]      = d0 * rs * lnw[lane]      + lnb[lane];
    sh[wid][lane + 32] = d1 * rs * lnw[lane + 32] + lnb[lane + 32];
    __syncwarp();

    float a0 = bin[lane], a1 = bin[lane + 32];
    const float* w0 = Win + lane * 64;
    const float* w1 = Win + (lane + 32) * 64;
    #pragma unroll 8
    for (int e = 0; e < 64; e++) {
        float he = sh[wid][e];
        a0 += w0[e] * he;
        a1 += w1[e] * he;
    }
    float* o = ph + ((long long)bn * NHEAD + wid) * HDIM;
    o[lane]      = gelu_f(a0);
    o[lane + 32] = gelu_f(a1);
}

__global__ void p2_k(const float* __restrict__ ph, const float* __restrict__ pol,
                     const float* __restrict__ den, float* __restrict__ glob)
{
    int bh = blockIdx.x;
    int b = bh / NHEAD, h = bh % NHEAD;
    int tid = threadIdx.x;
    int d = tid & 31, seg = tid >> 5;
    float s = 0.f;
    for (int n = seg; n < NSP; n += 8)
        s += ph[(((long long)(b * NSP + n)) * NHEAD + h) * HDIM + 32 + d]
             * pol[b * NTOK + 1 + n];
    __shared__ float sh[8][32];
    sh[seg][d] = s;
    __syncthreads();
    if (seg == 0) {
        float t = 0.f;
        #pragma unroll
        for (int k = 0; k < 8; k++) t += sh[k][d];
        glob[(b * NHEAD + h) * 32 + d] = t / den[b];
    }
}

__global__ void p3_k(const float* __restrict__ ph, const float* __restrict__ glob,
                     const float* __restrict__ W1, const float* __restrict__ b1,
                     const float* __restrict__ W2, const float* __restrict__ b2,
                     const float* __restrict__ W3, const float* __restrict__ b3,
                     const float* __restrict__ gum, float* __restrict__ pol)
{
    int bn = blockIdx.x;
    int b = bn / NSP, n = bn % NSP;
    int wid = threadIdx.x >> 5, lane = threadIdx.x & 31;
    __shared__ float h2[NHEAD][64];
    __shared__ float o1[NHEAD][32];
    __shared__ float o2[NHEAD][16];
    __shared__ float zz[NHEAD][2];

    const float* hin = ph + ((long long)bn * NHEAD + wid) * HDIM;
    h2[wid][lane]      = hin[lane];
    h2[wid][32 + lane] = glob[(b * NHEAD + wid) * 32 + lane];
    __syncwarp();
    {
        float a = b1[lane];
        const float* wr = W1 + lane * 64;
        #pragma unroll 8
        for (int e = 0; e < 64; e++) a += wr[e] * h2[wid][e];
        o1[wid][lane] = gelu_f(a);
    }
    __syncwarp();
    if (lane < 16) {
        float a = b2[lane];
        const float* wr = W2 + lane * 32;
        #pragma unroll 8
        for (int e = 0; e < 32; e++) a += wr[e] * o1[wid][e];
        o2[wid][lane] = gelu_f(a);
    }
    __syncwarp();
    if (lane < 2) {
        float a = b3[lane];
        const float* wr = W3 + lane * 16;
        #pragma unroll
        for (int e = 0; e < 16; e++) a += wr[e] * o2[wid][e];
        zz[wid][lane] = a;
    }
    __syncthreads();
    if (threadIdx.x == 0) {
        float s0 = 0.f, s1 = 0.f;
        #pragma unroll
        for (int h = 0; h < NHEAD; h++) {
            float z0 = zz[h][0], z1 = zz[h][1];
            float mx = fmaxf(z0, z1);
            float lse = mx + logf(expf(z0 - mx) + expf(z1 - mx));
            s0 += z0 - lse;
            s1 += z1 - lse;
        }
        s0 *= (1.f / 6.f); s1 *= (1.f / 6.f);
        float u0 = gum[((long long)b * NSP + n) * 2 + 0];
        float u1 = gum[((long long)b * NSP + n) * 2 + 1];
        float g0 = -logf(-logf(u0 + 1e-10f) + 1e-10f);
        float g1 = -logf(-logf(u1 + 1e-10f) + 1e-10f);
        int idx = b * NTOK + 1 + n;
        float keep = (s0 + g0 >= s1 + g1) ? pol[idx] : 0.f;
        pol[idx] = keep;
    }
}

/* ---------------- host-side ------------------------------------------------ */
static void launch_tcgemm(int epi,
                          const float* A, const float* B, const float* bias,
                          const float* R, float* C,
                          int M, int N, int K, int lda, int ldb, int ldc)
{
    dim3 g(N / 128, M / 128);
    if (epi == 0)      tcgemm_k<0><<<g, 256>>>(A, B, bias, R, C, K, lda, ldb, ldc);
    else if (epi == 1) tcgemm_k<1><<<g, 256>>>(A, B, bias, R, C, K, lda, ldb, ldc);
    else               tcgemm_k<2><<<g, 256>>>(A, B, bias, R, C, K, lda, ldb, ldc);
}

extern "C" void kernel_launch(void* const* d_in, const int* in_sizes, int n_in,
                              void* d_out, int out_size)
{
    const float* in_x     = (const float*)d_in[0];
    const float* in_cls   = (const float*)d_in[1];
    const float* in_pol   = (const float*)d_in[2];
    const float* in_gum   = (const float*)d_in[3];
    const float* ln1_w    = (const float*)d_in[4];
    const float* ln1_b    = (const float*)d_in[5];
    const float* qkv_w    = (const float*)d_in[6];
    const float* qkv_b    = (const float*)d_in[7];
    const float* proj_w   = (const float*)d_in[8];
    const float* proj_b   = (const float*)d_in[9];
    const float* ln2_w    = (const float*)d_in[10];
    const float* ln2_b    = (const float*)d_in[11];
    const float* fc1_w    = (const float*)d_in[12];
    const float* fc1_b    = (const float*)d_in[13];
    const float* fc2_w    = (const float*)d_in[14];
    const float* fc2_b    = (const float*)d_in[15];
    const float* p_ln_w   = (const float*)d_in[16];
    const float* p_ln_b   = (const float*)d_in[17];
    const float* p_in_w   = (const float*)d_in[18];
    const float* p_in_b   = (const float*)d_in[19];
    const float* p_o1_w   = (const float*)d_in[20];
    const float* p_o1_b   = (const float*)d_in[21];
    const float* p_o2_w   = (const float*)d_in[22];
    const float* p_o2_b   = (const float*)d_in[23];
    const float* p_o3_w   = (const float*)d_in[24];
    const float* p_o3_b   = (const float*)d_in[25];

    float *px, *phb, *pqkv, *pattn, *pao, *pffn, *ppol, *pph, *pglob, *pden;
    cudaGetSymbolAddress((void**)&px,    g_x);
    cudaGetSymbolAddress((void**)&phb,   g_h);
    cudaGetSymbolAddress((void**)&pqkv,  g_qkv);
    cudaGetSymbolAddress((void**)&pattn, g_attn);
    cudaGetSymbolAddress((void**)&pao,   g_ao);
    cudaGetSymbolAddress((void**)&pffn,  g_ffn);
    cudaGetSymbolAddress((void**)&ppol,  g_pol);
    cudaGetSymbolAddress((void**)&pph,   g_ph);
    cudaGetSymbolAddress((void**)&pglob, g_glob);
    cudaGetSymbolAddress((void**)&pden,  g_den);

    {
        long long total = (long long)MROWS * CDIM;
        int blocks = (int)((total + 255) / 256);
        init_x_k<<<blocks, 256>>>(in_x, in_cls, in_pol, px, ppol);
    }

    int pc = 0;
    for (int i = 0; i < DEPTHN; i++) {
        if (i == 3 || i == 6 || i == 9) {
            den_k<<<BATCH, 256>>>(ppol, pden);
            p1_k<<<BATCH * NSP, 192>>>(px,
                p_ln_w + pc * HDIM, p_ln_b + pc * HDIM,
                p_in_w + pc * HDIM * HDIM, p_in_b + pc * HDIM, pph);
            p2_k<<<BATCH * NHEAD, 256>>>(pph, ppol, pden, pglob);
            p3_k<<<BATCH * NSP, 192>>>(pph, pglob,
                p_o1_w + pc * 32 * 64, p_o1_b + pc * 32,
                p_o2_w + pc * 16 * 32, p_o2_b + pc * 16,
                p_o3_w + pc * 2 * 16,  p_o3_b + pc * 2,
                in_gum + (long long)pc * BATCH * NSP * 2, ppol);
            pc++;
        }

        ln_k<<<MROWS, 128>>>(px, ln1_w + i * CDIM, ln1_b + i * CDIM, phb, 1e-6f);

        launch_tcgemm(0, phb, qkv_w + (long long)i * QKVDIM * CDIM,
                      qkv_b + i * QKVDIM, nullptr, pqkv,
                      MROWS, QKVDIM, CDIM, CDIM, CDIM, QKVDIM);

        /* scores: per (b,h): Q[197,64] @ K[197,64]^T * 0.125 */
        gemm_k<true><<<dim3(2, 2, BATCH * NHEAD), 256>>>(
            pqkv, pqkv + CDIM, pattn,
            NTOK, NTOK, HDIM, QKVDIM, QKVDIM, NTOK, 0.125f,
            (long long)NTOK * QKVDIM, HDIM,
            (long long)NTOK * QKVDIM, HDIM,
            (long long)NHEAD * NTOK * NTOK, (long long)NTOK * NTOK);

        softmax_pol_k<<<BATCH * NHEAD * NTOK, 128>>>(pattn, ppol);

        /* O = A @ V : per (b,h): [197,197] @ [197,64] (NN) */
        gemm_k<false><<<dim3(1, 2, BATCH * NHEAD), 256>>>(
            pattn, pqkv + 2 * CDIM, pao,
            NTOK, HDIM, NTOK, NTOK, QKVDIM, CDIM, 1.0f,
            (long long)NHEAD * NTOK * NTOK, (long long)NTOK * NTOK,
            (long long)NTOK * QKVDIM, HDIM,
            (long long)NTOK * CDIM, HDIM);

        launch_tcgemm(2, pao, proj_w + (long long)i * CDIM * CDIM,
                      proj_b + i * CDIM, px, px,
                      MROWS, CDIM, CDIM, CDIM, CDIM, CDIM);

        ln_k<<<MROWS, 128>>>(px, ln2_w + i * CDIM, ln2_b + i * CDIM, phb, 1e-6f);

        launch_tcgemm(1, phb, fc1_w + (long long)i * FFDIM * CDIM,
                      fc1_b + i * FFDIM, nullptr, pffn,
                      MROWS, FFDIM, CDIM, CDIM, CDIM, FFDIM);

        launch_tcgemm(2, pffn, fc2_w + (long long)i * CDIM * FFDIM,
                      fc2_b + i * CDIM, px, px,
                      MROWS, CDIM, FFDIM, FFDIM, FFDIM, CDIM);
    }

    {
        long long total = (long long)BATCH * CDIM * NSP + (long long)BATCH * CDIM;
        int blocks = (int)((total + 255) / 256);
        final_k<<<blocks, 256>>>(px, (float*)d_out);
    }
}

// round 4
// speedup vs baseline: 2.8098x; 1.4070x over previous
#include <cuda_runtime.h>
#include <math.h>
#include <stdint.h>

#define DEPTHN 12
#define BATCH 128
#define NTOK 197
#define NSP 196
#define CDIM 384
#define NHEAD 6
#define HDIM 64
#define MROWS (BATCH*NTOK)      /* 25216 */
#define FFDIM 1536
#define QKVDIM 1152
#define ASTRIDE 224             /* padded attention row stride / rows per head */

/* ---------------- scratch (device globals; zero-initialized) ------------- */
__device__ float g_x   [MROWS*CDIM];
__device__ float g_h   [MROWS*CDIM];
__device__ float g_qkv [MROWS*QKVDIM];
__device__ float g_attn[(long long)BATCH*NHEAD*ASTRIDE*ASTRIDE]; /* zero pads persist */
__device__ float g_ao  [MROWS*CDIM];
__device__ float g_ffn [MROWS*FFDIM];
__device__ float g_pol [BATCH*NTOK];
__device__ float g_ph  [BATCH*NSP*NHEAD*HDIM];
__device__ float g_glob[BATCH*NHEAD*32];
__device__ float g_den [BATCH];

__device__ __forceinline__ float gelu_f(float x) {
    return 0.5f * x * (1.0f + erff(x * 0.70710678118654752440f));
}

__device__ __forceinline__ uint32_t f2tf32(float f) {
    uint32_t u;
    asm("cvt.rna.tf32.f32 %0, %1;" : "=r"(u) : "f"(f));
    return u;
}

__device__ __forceinline__ uint32_t smem_u32(const void* p) {
    uint32_t a;
    asm("{ .reg .u64 t; cvta.to.shared.u64 t, %1; cvt.u32.u64 %0, t; }" : "=r"(a) : "l"(p));
    return a;
}

__device__ __forceinline__ void cp_async16(uint32_t saddr, const void* g) {
    asm volatile("cp.async.cg.shared.global [%0], [%1], 16;" :: "r"(saddr), "l"(g));
}
#define CP_COMMIT() asm volatile("cp.async.commit_group;" ::: "memory")
#define CP_WAIT(n)  asm volatile("cp.async.wait_group %0;" :: "n"(n) : "memory")

__device__ __forceinline__ void mma_tf32_16n8k8(
    float& d0, float& d1, float& d2, float& d3,
    uint32_t a0, uint32_t a1, uint32_t a2, uint32_t a3,
    uint32_t b0, uint32_t b1)
{
    asm volatile(
        "mma.sync.aligned.m16n8k8.row.col.f32.tf32.tf32.f32 "
        "{%0,%1,%2,%3}, {%4,%5,%6,%7}, {%8,%9}, {%0,%1,%2,%3};"
        : "+f"(d0), "+f"(d1), "+f"(d2), "+f"(d3)
        : "r"(a0), "r"(a1), "r"(a2), "r"(a3), "r"(b0), "r"(b1));
}

/* ================= dense HMMA tf32 GEMM (cp.async double-buffered) =======
 * C[m,n] = sum_k A[m,k]*B[n,k] + bias[n]   (EPI: 0 none, 1 gelu, 2 +R)
 * M%128==0, N%128==0, K%32==0. 256 threads, 8 warps (2M x 4N), warp 64x32.
 * dynamic smem: 2 stages x (As[128][36] + Bs[128][36]) fp32 = 73728 B.
 */
#define DENSE_SMEM 73728

template<int EPI>
__global__ void __launch_bounds__(256, 2)
tcgemm_k(const float* __restrict__ A, const float* __restrict__ B,
         const float* __restrict__ bias, const float* __restrict__ R,
         float* __restrict__ C, int K, int lda, int ldb, int ldc)
{
    extern __shared__ float dsm[];
    float* As = dsm;                 /* [2][128*36] */
    float* Bs = dsm + 2 * 128 * 36;
    const uint32_t asb = smem_u32(As);
    const uint32_t bsb = smem_u32(Bs);

    const int tid = threadIdx.x, wid = tid >> 5, lane = tid & 31;
    const int lane4 = lane >> 2, lanek = lane & 3;
    const int warpM = wid & 1, warpN = wid >> 1;
    const int m0 = blockIdx.y * 128, n0 = blockIdx.x * 128;
    const int lrow = tid >> 3, lkq = tid & 7;

    float acc[4][4][4];
    #pragma unroll
    for (int i = 0; i < 4; i++)
        #pragma unroll
        for (int j = 0; j < 4; j++)
            #pragma unroll
            for (int r = 0; r < 4; r++) acc[i][j][r] = 0.f;

#define ISSUE(t_, s_) do {                                                       \
    int k0_ = (t_) * 32;                                                         \
    _Pragma("unroll")                                                            \
    for (int i_ = 0; i_ < 4; i_++) {                                             \
        int row_ = lrow + 32 * i_;                                               \
        uint32_t so_ = (uint32_t)(((s_) * 4608 + row_ * 36 + lkq * 4) * 4);      \
        cp_async16(asb + so_, A + (size_t)(m0 + row_) * lda + k0_ + lkq * 4);    \
        cp_async16(bsb + so_, B + (size_t)(n0 + row_) * ldb + k0_ + lkq * 4);    \
    }                                                                            \
    CP_COMMIT();                                                                 \
} while (0)

    const int T = K >> 5;
    ISSUE(0, 0);

    for (int t = 0; t < T; t++) {
        int p = t & 1;
        if (t + 1 < T) { ISSUE(t + 1, p ^ 1); CP_WAIT(1); }
        else           { CP_WAIT(0); }
        __syncthreads();

        const float* Ap = As + p * 4608;
        const float* Bp = Bs + p * 4608;
        #pragma unroll
        for (int ks = 0; ks < 4; ks++) {
            const int kk = ks * 8 + lanek;
            uint32_t a[4][4], b[4][2];
            #pragma unroll
            for (int mf = 0; mf < 4; mf++) {
                int rb = warpM * 64 + mf * 16 + lane4;
                a[mf][0] = f2tf32(Ap[rb * 36 + kk]);
                a[mf][1] = f2tf32(Ap[(rb + 8) * 36 + kk]);
                a[mf][2] = f2tf32(Ap[rb * 36 + kk + 4]);
                a[mf][3] = f2tf32(Ap[(rb + 8) * 36 + kk + 4]);
            }
            #pragma unroll
            for (int nf = 0; nf < 4; nf++) {
                int nb = warpN * 32 + nf * 8 + lane4;
                b[nf][0] = f2tf32(Bp[nb * 36 + kk]);
                b[nf][1] = f2tf32(Bp[nb * 36 + kk + 4]);
            }
            #pragma unroll
            for (int mf = 0; mf < 4; mf++)
                #pragma unroll
                for (int nf = 0; nf < 4; nf++)
                    mma_tf32_16n8k8(acc[mf][nf][0], acc[mf][nf][1],
                                    acc[mf][nf][2], acc[mf][nf][3],
                                    a[mf][0], a[mf][1], a[mf][2], a[mf][3],
                                    b[nf][0], b[nf][1]);
        }
        if (t + 1 < T) __syncthreads();
    }
#undef ISSUE

    /* epilogue */
    #pragma unroll
    for (int mf = 0; mf < 4; mf++) {
        int m = m0 + warpM * 64 + mf * 16 + lane4;
        #pragma unroll
        for (int nf = 0; nf < 4; nf++) {
            int n = n0 + warpN * 32 + nf * 8 + lanek * 2;
            float bz0 = bias ? __ldg(bias + n)     : 0.f;
            float bz1 = bias ? __ldg(bias + n + 1) : 0.f;
            size_t gi0 = (size_t)m * ldc + n;
            size_t gi1 = (size_t)(m + 8) * ldc + n;
            float v0 = acc[mf][nf][0] + bz0;
            float v1 = acc[mf][nf][1] + bz1;
            float v2 = acc[mf][nf][2] + bz0;
            float v3 = acc[mf][nf][3] + bz1;
            if (EPI == 1) {
                v0 = gelu_f(v0); v1 = gelu_f(v1);
                v2 = gelu_f(v2); v3 = gelu_f(v3);
            } else if (EPI == 2) {
                v0 += R[gi0]; v1 += R[gi0 + 1];
                v2 += R[gi1]; v3 += R[gi1 + 1];
            }
            *(float2*)(C + gi0) = make_float2(v0, v1);
            *(float2*)(C + gi1) = make_float2(v2, v3);
        }
    }
}

/* ================= attention scores: S = Q @ K^T * 0.125 (HMMA) ==========
 * per (b,h): [197,64] @ [197,64]^T -> [197,197] stored with row stride 224.
 * grid (2,2,768), 256 threads. smem: Qs[128][68] + Ks[128][68] tf32 = 69632 B.
 */
#define SCORE_SMEM 69632

__global__ void __launch_bounds__(256)
score_k(const float* __restrict__ qkv, float* __restrict__ attn)
{
    extern __shared__ uint32_t ssm[];
    uint32_t* Qs = ssm;             /* [128][68] */
    uint32_t* Ks = ssm + 128 * 68;

    const int tid = threadIdx.x, wid = tid >> 5, lane = tid & 31;
    const int lane4 = lane >> 2, lanek = lane & 3;
    const int warpM = wid & 1, warpN = wid >> 1;
    const int bh = blockIdx.z, b = bh / NHEAD, h = bh % NHEAD;
    const int m0 = blockIdx.y * 128, n0 = blockIdx.x * 128;

    const float* qb = qkv + (size_t)b * NTOK * QKVDIM + h * HDIM;
    const float* kb = qb + CDIM;

    /* load Q/K tiles (guarded rows), convert to tf32 */
    #pragma unroll
    for (int p = 0; p < 2; p++) {
        int row = (tid >> 2) + p * 64;
        #pragma unroll
        for (int i = 0; i < 4; i++) {
            int col = (tid & 3) * 16 + i * 4;
            float4 vq = make_float4(0.f, 0.f, 0.f, 0.f);
            float4 vk = make_float4(0.f, 0.f, 0.f, 0.f);
            if (m0 + row < NTOK) vq = *(const float4*)(qb + (size_t)(m0 + row) * QKVDIM + col);
            if (n0 + row < NTOK) vk = *(const float4*)(kb + (size_t)(n0 + row) * QKVDIM + col);
            uint32_t* pq = Qs + row * 68 + col;
            uint32_t* pk = Ks + row * 68 + col;
            pq[0] = f2tf32(vq.x); pq[1] = f2tf32(vq.y); pq[2] = f2tf32(vq.z); pq[3] = f2tf32(vq.w);
            pk[0] = f2tf32(vk.x); pk[1] = f2tf32(vk.y); pk[2] = f2tf32(vk.z); pk[3] = f2tf32(vk.w);
        }
    }
    __syncthreads();

    float acc[4][4][4];
    #pragma unroll
    for (int i = 0; i < 4; i++)
        #pragma unroll
        for (int j = 0; j < 4; j++)
            #pragma unroll
            for (int r = 0; r < 4; r++) acc[i][j][r] = 0.f;

    #pragma unroll
    for (int ks = 0; ks < 8; ks++) {
        const int kk = ks * 8 + lanek;
        uint32_t a[4][4], bb[4][2];
        #pragma unroll
        for (int mf = 0; mf < 4; mf++) {
            int rb = warpM * 64 + mf * 16 + lane4;
            a[mf][0] = Qs[rb * 68 + kk];
            a[mf][1] = Qs[(rb + 8) * 68 + kk];
            a[mf][2] = Qs[rb * 68 + kk + 4];
            a[mf][3] = Qs[(rb + 8) * 68 + kk + 4];
        }
        #pragma unroll
        for (int nf = 0; nf < 4; nf++) {
            int nb = warpN * 32 + nf * 8 + lane4;
            bb[nf][0] = Ks[nb * 68 + kk];
            bb[nf][1] = Ks[nb * 68 + kk + 4];
        }
        #pragma unroll
        for (int mf = 0; mf < 4; mf++)
            #pragma unroll
            for (int nf = 0; nf < 4; nf++)
                mma_tf32_16n8k8(acc[mf][nf][0], acc[mf][nf][1],
                                acc[mf][nf][2], acc[mf][nf][3],
                                a[mf][0], a[mf][1], a[mf][2], a[mf][3],
                                bb[nf][0], bb[nf][1]);
    }

    float* ab = attn + (size_t)bh * ASTRIDE * ASTRIDE;
    #pragma unroll
    for (int mf = 0; mf < 4; mf++) {
        int m = m0 + warpM * 64 + mf * 16 + lane4;
        #pragma unroll
        for (int nf = 0; nf < 4; nf++) {
            int n = n0 + warpN * 32 + nf * 8 + lanek * 2;
            if (m < NTOK) {
                if (n < NTOK)     ab[(size_t)m * ASTRIDE + n]     = 0.125f * acc[mf][nf][0];
                if (n + 1 < NTOK) ab[(size_t)m * ASTRIDE + n + 1] = 0.125f * acc[mf][nf][1];
            }
            if (m + 8 < NTOK) {
                if (n < NTOK)     ab[(size_t)(m + 8) * ASTRIDE + n]     = 0.125f * acc[mf][nf][2];
                if (n + 1 < NTOK) ab[(size_t)(m + 8) * ASTRIDE + n + 1] = 0.125f * acc[mf][nf][3];
            }
        }
    }
}

/* ================= AV: O = P @ V (HMMA) ===================================
 * per (b,h): [197,224pad] @ [197,64] -> [197,64] into [B,N,H,HD] layout.
 * grid (1,2,768), 256 threads, 8 warps (4M x 2N), warp 32x32.
 */
__global__ void __launch_bounds__(256)
av_k(const float* __restrict__ attn, const float* __restrict__ qkv,
     float* __restrict__ ao)
{
    __shared__ uint32_t As[128 * 36];
    __shared__ uint32_t Vs[64 * 36];

    const int tid = threadIdx.x, wid = tid >> 5, lane = tid & 31;
    const int lane4 = lane >> 2, lanek = lane & 3;
    const int warpM = wid >> 1, warpN = wid & 1;
    const int bh = blockIdx.z, b = bh / NHEAD, h = bh % NHEAD;
    const int m0 = blockIdx.y * 128;

    const float* ab = attn + (size_t)bh * ASTRIDE * ASTRIDE;
    const float* vb = qkv + (size_t)b * NTOK * QKVDIM + h * HDIM + 2 * CDIM;

    float acc[2][4][4];
    #pragma unroll
    for (int i = 0; i < 2; i++)
        #pragma unroll
        for (int j = 0; j < 4; j++)
            #pragma unroll
            for (int r = 0; r < 4; r++) acc[i][j][r] = 0.f;

    for (int t = 0; t < 7; t++) {
        const int k0 = t * 32;
        /* A tile 128x32 (rows guarded; pad cols are zero in attn) */
        #pragma unroll
        for (int p = 0; p < 2; p++) {
            int row = (tid >> 2) + p * 64;
            int m = m0 + row;
            #pragma unroll
            for (int i = 0; i < 2; i++) {
                int col = (tid & 3) * 8 + i * 4;
                float4 v = make_float4(0.f, 0.f, 0.f, 0.f);
                if (m < NTOK) v = *(const float4*)(ab + (size_t)m * ASTRIDE + k0 + col);
                uint32_t* pa = As + row * 36 + col;
                pa[0] = f2tf32(v.x); pa[1] = f2tf32(v.y);
                pa[2] = f2tf32(v.z); pa[3] = f2tf32(v.w);
            }
        }
        /* V tile 32k x 64n, transposed into Vs[n][kk] (k rows guarded) */
        {
            int n = tid & 63;
            #pragma unroll
            for (int i = 0; i < 8; i++) {
                int kk = (tid >> 6) + 4 * i;
                int kg = k0 + kk;
                float v = (kg < NTOK) ? vb[(size_t)kg * QKVDIM + n] : 0.f;
                Vs[n * 36 + kk] = f2tf32(v);
            }
        }
        __syncthreads();

        #pragma unroll
        for (int ks = 0; ks < 4; ks++) {
            const int kk = ks * 8 + lanek;
            uint32_t a[2][4], bb[4][2];
            #pragma unroll
            for (int mf = 0; mf < 2; mf++) {
                int rb = warpM * 32 + mf * 16 + lane4;
                a[mf][0] = As[rb * 36 + kk];
                a[mf][1] = As[(rb + 8) * 36 + kk];
                a[mf][2] = As[rb * 36 + kk + 4];
                a[mf][3] = As[(rb + 8) * 36 + kk + 4];
            }
            #pragma unroll
            for (int nf = 0; nf < 4; nf++) {
                int nb = warpN * 32 + nf * 8 + lane4;
                bb[nf][0] = Vs[nb * 36 + kk];
                bb[nf][1] = Vs[nb * 36 + kk + 4];
            }
            #pragma unroll
            for (int mf = 0; mf < 2; mf++)
                #pragma unroll
                for (int nf = 0; nf < 4; nf++)
                    mma_tf32_16n8k8(acc[mf][nf][0], acc[mf][nf][1],
                                    acc[mf][nf][2], acc[mf][nf][3],
                                    a[mf][0], a[mf][1], a[mf][2], a[mf][3],
                                    bb[nf][0], bb[nf][1]);
        }
        __syncthreads();
    }

    #pragma unroll
    for (int mf = 0; mf < 2; mf++) {
        int m = m0 + warpM * 32 + mf * 16 + lane4;
        #pragma unroll
        for (int nf = 0; nf < 4; nf++) {
            int n = warpN * 32 + nf * 8 + lanek * 2;
            if (m < NTOK)
                *(float2*)(ao + (size_t)(b * NTOK + m) * CDIM + h * HDIM + n) =
                    make_float2(acc[mf][nf][0], acc[mf][nf][1]);
            if (m + 8 < NTOK)
                *(float2*)(ao + (size_t)(b * NTOK + m + 8) * CDIM + h * HDIM + n) =
                    make_float2(acc[mf][nf][2], acc[mf][nf][3]);
        }
    }
}

/* ---------------- block reductions --------------------------------------- */
__device__ __forceinline__ float blockReduceSum(float v, float* sh) {
    int tid = threadIdx.x, lane = tid & 31, w = tid >> 5;
    #pragma unroll
    for (int o = 16; o; o >>= 1) v += __shfl_xor_sync(0xffffffffu, v, o);
    if (lane == 0) sh[w] = v;
    __syncthreads();
    int nw = (blockDim.x + 31) >> 5;
    v = (tid < nw) ? sh[tid] : 0.f;
    if (w == 0) {
        #pragma unroll
        for (int o = 16; o; o >>= 1) v += __shfl_xor_sync(0xffffffffu, v, o);
        if (lane == 0) sh[0] = v;
    }
    __syncthreads();
    float r = sh[0];
    __syncthreads();
    return r;
}

/* ---------------- warp-per-row policy softmax ----------------------------- */
__global__ void __launch_bounds__(256)
softmax_pol_k(float* __restrict__ attn, const float* __restrict__ pol)
{
    int wid = threadIdx.x >> 5, lane = threadIdx.x & 31;
    long long r = (long long)blockIdx.x * 8 + wid;   /* over 768*197 rows */
    int bh = (int)(r / NTOK), n = (int)(r % NTOK);
    int b = bh / NHEAD;
    float* row = attn + ((size_t)bh * ASTRIDE + n) * ASTRIDE;
    const float* pb = pol + b * NTOK;

    float v[7];
    float mx = -1e30f;
    #pragma unroll
    for (int i = 0; i < 7; i++) {
        int m = lane + 32 * i;
        v[i] = (m < NTOK) ? row[m] : -1e30f;
        mx = fmaxf(mx, v[i]);
    }
    #pragma unroll
    for (int o = 16; o; o >>= 1) mx = fmaxf(mx, __shfl_xor_sync(0xffffffffu, mx, o));

    float sum = 0.f;
    #pragma unroll
    for (int i = 0; i < 7; i++) {
        int m = lane + 32 * i;
        if (m < NTOK) {
            float ap = (m == n) ? 1.0f : pb[m];
            float e = expf(v[i] - mx) * ap;
            v[i] = e;
            sum += e;
        }
    }
    #pragma unroll
    for (int o = 16; o; o >>= 1) sum += __shfl_xor_sync(0xffffffffu, sum, o);
    float inv = 1.0f / sum;
    #pragma unroll
    for (int i = 0; i < 7; i++) {
        int m = lane + 32 * i;
        if (m < NTOK) row[m] = v[i] * inv;
    }
}

/* ---------------- LayerNorm over C=384 ----------------------------------- */
__global__ void ln_k(const float* __restrict__ x, const float* __restrict__ w,
                     const float* __restrict__ bb, float* __restrict__ out, float eps)
{
    __shared__ float sh[32];
    long long row = blockIdx.x;
    const float* xr = x + row * CDIM;
    int tid = threadIdx.x; /* 128 */
    float v0 = xr[tid], v1 = xr[tid + 128], v2 = xr[tid + 256];
    float s = blockReduceSum(v0 + v1 + v2, sh);
    float m = s * (1.f / 384.f);
    float d0 = v0 - m, d1 = v1 - m, d2 = v2 - m;
    float q = blockReduceSum(d0*d0 + d1*d1 + d2*d2, sh);
    float rs = rsqrtf(q * (1.f / 384.f) + eps);
    float* orow = out + row * CDIM;
    orow[tid]       = d0 * rs * w[tid]       + bb[tid];
    orow[tid + 128] = d1 * rs * w[tid + 128] + bb[tid + 128];
    orow[tid + 256] = d2 * rs * w[tid + 256] + bb[tid + 256];
}

/* ---------------- init / final ------------------------------------------- */
__global__ void init_x_k(const float* __restrict__ xin, const float* __restrict__ cls,
                         const float* __restrict__ polin,
                         float* __restrict__ x, float* __restrict__ pol)
{
    long long idx = (long long)blockIdx.x * blockDim.x + threadIdx.x;
    long long total = (long long)MROWS * CDIM;
    if (idx < total) {
        int c  = (int)(idx % CDIM);
        int nn = (int)((idx / CDIM) % NTOK);
        int b  = (int)(idx / ((long long)CDIM * NTOK));
        float v;
        if (nn == 0) v = cls[b * CDIM + c];
        else         v = xin[((long long)b * CDIM + c) * NSP + (nn - 1)];
        x[idx] = v;
    }
    if (idx < BATCH * NTOK) pol[idx] = polin[idx];
}

__global__ void final_k(const float* __restrict__ x, float* __restrict__ out)
{
    long long idx = (long long)blockIdx.x * blockDim.x + threadIdx.x;
    const long long total_sp = (long long)BATCH * CDIM * NSP;
    if (idx < total_sp) {
        int hw = (int)(idx % NSP);
        int c  = (int)((idx / NSP) % CDIM);
        int b  = (int)(idx / ((long long)NSP * CDIM));
        out[idx] = x[((long long)(b * NTOK) + 1 + hw) * CDIM + c];
    } else if (idx < total_sp + (long long)BATCH * CDIM) {
        long long rr = idx - total_sp;
        int c = (int)(rr % CDIM);
        int b = (int)(rr / CDIM);
        out[idx] = x[((long long)b * NTOK) * CDIM + c];
    }
}

/* ---------------- predictor --------------------------------------------- */
__global__ void den_k(const float* __restrict__ pol, float* __restrict__ den)
{
    __shared__ float sh[32];
    int b = blockIdx.x;
    int tid = threadIdx.x;
    float v = (tid < NSP) ? pol[b * NTOK + 1 + tid] : 0.f;
    float s = blockReduceSum(v, sh);
    if (tid == 0) den[b] = s;
}

__global__ void p1_k(const float* __restrict__ x,
                     const float* __restrict__ lnw, const float* __restrict__ lnb,
                     const float* __restrict__ Win, const float* __restrict__ bin,
                     float* __restrict__ ph)
{
    int bn = blockIdx.x;
    int b = bn / NSP, n = bn % NSP;
    int wid = threadIdx.x >> 5, lane = threadIdx.x & 31;
    __shared__ float sh[NHEAD][HDIM];

    const float* xr = x + ((long long)(b * NTOK + 1 + n)) * CDIM + wid * HDIM;
    float v0 = xr[lane], v1 = xr[lane + 32];
    float s = v0 + v1;
    #pragma unroll
    for (int o = 16; o; o >>= 1) s += __shfl_xor_sync(0xffffffffu, s, o);
    float m = s * (1.f / 64.f);
    float d0 = v0 - m, d1 = v1 - m;
    float q = d0*d0 + d1*d1;
    #pragma unroll
    for (int o = 16; o; o >>= 1) q += __shfl_xor_sync(0xffffffffu, q, o);
    float rs = rsqrtf(q * (1.f / 64.f) + 1e-5f);
    sh[wid][lane]      = d0 * rs * lnw[lane]      + lnb[lane];
    sh[wid][lane + 32] = d1 * rs * lnw[lane + 32] + lnb[lane + 32];
    __syncwarp();

    float a0 = bin[lane], a1 = bin[lane + 32];
    const float* w0 = Win + lane * 64;
    const float* w1 = Win + (lane + 32) * 64;
    #pragma unroll 8
    for (int e = 0; e < 64; e++) {
        float he = sh[wid][e];
        a0 += w0[e] * he;
        a1 += w1[e] * he;
    }
    float* o = ph + ((long long)bn * NHEAD + wid) * HDIM;
    o[lane]      = gelu_f(a0);
    o[lane + 32] = gelu_f(a1);
}

__global__ void p2_k(const float* __restrict__ ph, const float* __restrict__ pol,
                     const float* __restrict__ den, float* __restrict__ glob)
{
    int bh = blockIdx.x;
    int b = bh / NHEAD, h = bh % NHEAD;
    int tid = threadIdx.x;
    int d = tid & 31, seg = tid >> 5;
    float s = 0.f;
    for (int n = seg; n < NSP; n += 8)
        s += ph[(((long long)(b * NSP + n)) * NHEAD + h) * HDIM + 32 + d]
             * pol[b * NTOK + 1 + n];
    __shared__ float sh[8][32];
    sh[seg][d] = s;
    __syncthreads();
    if (seg == 0) {
        float t = 0.f;
        #pragma unroll
        for (int k = 0; k < 8; k++) t += sh[k][d];
        glob[(b * NHEAD + h) * 32 + d] = t / den[b];
    }
}

__global__ void p3_k(const float* __restrict__ ph, const float* __restrict__ glob,
                     const float* __restrict__ W1, const float* __restrict__ b1,
                     const float* __restrict__ W2, const float* __restrict__ b2,
                     const float* __restrict__ W3, const float* __restrict__ b3,
                     const float* __restrict__ gum, float* __restrict__ pol)
{
    int bn = blockIdx.x;
    int b = bn / NSP, n = bn % NSP;
    int wid = threadIdx.x >> 5, lane = threadIdx.x & 31;
    __shared__ float h2[NHEAD][64];
    __shared__ float o1[NHEAD][32];
    __shared__ float o2[NHEAD][16];
    __shared__ float zz[NHEAD][2];

    const float* hin = ph + ((long long)bn * NHEAD + wid) * HDIM;
    h2[wid][lane]      = hin[lane];
    h2[wid][32 + lane] = glob[(b * NHEAD + wid) * 32 + lane];
    __syncwarp();
    {
        float a = b1[lane];
        const float* wr = W1 + lane * 64;
        #pragma unroll 8
        for (int e = 0; e < 64; e++) a += wr[e] * h2[wid][e];
        o1[wid][lane] = gelu_f(a);
    }
    __syncwarp();
    if (lane < 16) {
        float a = b2[lane];
        const float* wr = W2 + lane * 32;
        #pragma unroll 8
        for (int e = 0; e < 32; e++) a += wr[e] * o1[wid][e];
        o2[wid][lane] = gelu_f(a);
    }
    __syncwarp();
    if (lane < 2) {
        float a = b3[lane];
        const float* wr = W3 + lane * 16;
        #pragma unroll
        for (int e = 0; e < 16; e++) a += wr[e] * o2[wid][e];
        zz[wid][lane] = a;
    }
    __syncthreads();
    if (threadIdx.x == 0) {
        float s0 = 0.f, s1 = 0.f;
        #pragma unroll
        for (int h = 0; h < NHEAD; h++) {
            float z0 = zz[h][0], z1 = zz[h][1];
            float mx = fmaxf(z0, z1);
            float lse = mx + logf(expf(z0 - mx) + expf(z1 - mx));
            s0 += z0 - lse;
            s1 += z1 - lse;
        }
        s0 *= (1.f / 6.f); s1 *= (1.f / 6.f);
        float u0 = gum[((long long)b * NSP + n) * 2 + 0];
        float u1 = gum[((long long)b * NSP + n) * 2 + 1];
        float g0 = -logf(-logf(u0 + 1e-10f) + 1e-10f);
        float g1 = -logf(-logf(u1 + 1e-10f) + 1e-10f);
        int idx = b * NTOK + 1 + n;
        float keep = (s0 + g0 >= s1 + g1) ? pol[idx] : 0.f;
        pol[idx] = keep;
    }
}

/* ---------------- host-side ------------------------------------------------ */
static void launch_tcgemm(int epi,
                          const float* A, const float* B, const float* bias,
                          const float* R, float* C,
                          int M, int N, int K, int lda, int ldb, int ldc)
{
    dim3 g(N / 128, M / 128);
    if (epi == 0)      tcgemm_k<0><<<g, 256, DENSE_SMEM>>>(A, B, bias, R, C, K, lda, ldb, ldc);
    else if (epi == 1) tcgemm_k<1><<<g, 256, DENSE_SMEM>>>(A, B, bias, R, C, K, lda, ldb, ldc);
    else               tcgemm_k<2><<<g, 256, DENSE_SMEM>>>(A, B, bias, R, C, K, lda, ldb, ldc);
}

extern "C" void kernel_launch(void* const* d_in, const int* in_sizes, int n_in,
                              void* d_out, int out_size)
{
    const float* in_x     = (const float*)d_in[0];
    const float* in_cls   = (const float*)d_in[1];
    const float* in_pol   = (const float*)d_in[2];
    const float* in_gum   = (const float*)d_in[3];
    const float* ln1_w    = (const float*)d_in[4];
    const float* ln1_b    = (const float*)d_in[5];
    const float* qkv_w    = (const float*)d_in[6];
    const float* qkv_b    = (const float*)d_in[7];
    const float* proj_w   = (const float*)d_in[8];
    const float* proj_b   = (const float*)d_in[9];
    const float* ln2_w    = (const float*)d_in[10];
    const float* ln2_b    = (const float*)d_in[11];
    const float* fc1_w    = (const float*)d_in[12];
    const float* fc1_b    = (const float*)d_in[13];
    const float* fc2_w    = (const float*)d_in[14];
    const float* fc2_b    = (const float*)d_in[15];
    const float* p_ln_w   = (const float*)d_in[16];
    const float* p_ln_b   = (const float*)d_in[17];
    const float* p_in_w   = (const float*)d_in[18];
    const float* p_in_b   = (const float*)d_in[19];
    const float* p_o1_w   = (const float*)d_in[20];
    const float* p_o1_b   = (const float*)d_in[21];
    const float* p_o2_w   = (const float*)d_in[22];
    const float* p_o2_b   = (const float*)d_in[23];
    const float* p_o3_w   = (const float*)d_in[24];
    const float* p_o3_b   = (const float*)d_in[25];

    cudaFuncSetAttribute(tcgemm_k<0>, cudaFuncAttributeMaxDynamicSharedMemorySize, DENSE_SMEM);
    cudaFuncSetAttribute(tcgemm_k<1>, cudaFuncAttributeMaxDynamicSharedMemorySize, DENSE_SMEM);
    cudaFuncSetAttribute(tcgemm_k<2>, cudaFuncAttributeMaxDynamicSharedMemorySize, DENSE_SMEM);
    cudaFuncSetAttribute(score_k,     cudaFuncAttributeMaxDynamicSharedMemorySize, SCORE_SMEM);

    float *px, *phb, *pqkv, *pattn, *pao, *pffn, *ppol, *pph, *pglob, *pden;
    cudaGetSymbolAddress((void**)&px,    g_x);
    cudaGetSymbolAddress((void**)&phb,   g_h);
    cudaGetSymbolAddress((void**)&pqkv,  g_qkv);
    cudaGetSymbolAddress((void**)&pattn, g_attn);
    cudaGetSymbolAddress((void**)&pao,   g_ao);
    cudaGetSymbolAddress((void**)&pffn,  g_ffn);
    cudaGetSymbolAddress((void**)&ppol,  g_pol);
    cudaGetSymbolAddress((void**)&pph,   g_ph);
    cudaGetSymbolAddress((void**)&pglob, g_glob);
    cudaGetSymbolAddress((void**)&pden,  g_den);

    {
        long long total = (long long)MROWS * CDIM;
        int blocks = (int)((total + 255) / 256);
        init_x_k<<<blocks, 256>>>(in_x, in_cls, in_pol, px, ppol);
    }

    int pc = 0;
    for (int i = 0; i < DEPTHN; i++) {
        if (i == 3 || i == 6 || i == 9) {
            den_k<<<BATCH, 256>>>(ppol, pden);
            p1_k<<<BATCH * NSP, 192>>>(px,
                p_ln_w + pc * HDIM, p_ln_b + pc * HDIM,
                p_in_w + pc * HDIM * HDIM, p_in_b + pc * HDIM, pph);
            p2_k<<<BATCH * NHEAD, 256>>>(pph, ppol, pden, pglob);
            p3_k<<<BATCH * NSP, 192>>>(pph, pglob,
                p_o1_w + pc * 32 * 64, p_o1_b + pc * 32,
                p_o2_w + pc * 16 * 32, p_o2_b + pc * 16,
                p_o3_w + pc * 2 * 16,  p_o3_b + pc * 2,
                in_gum + (long long)pc * BATCH * NSP * 2, ppol);
            pc++;
        }

        ln_k<<<MROWS, 128>>>(px, ln1_w + i * CDIM, ln1_b + i * CDIM, phb, 1e-6f);

        launch_tcgemm(0, phb, qkv_w + (long long)i * QKVDIM * CDIM,
                      qkv_b + i * QKVDIM, nullptr, pqkv,
                      MROWS, QKVDIM, CDIM, CDIM, CDIM, QKVDIM);

        score_k<<<dim3(2, 2, BATCH * NHEAD), 256, SCORE_SMEM>>>(pqkv, pattn);

        softmax_pol_k<<<(BATCH * NHEAD * NTOK) / 8, 256>>>(pattn, ppol);

        av_k<<<dim3(1, 2, BATCH * NHEAD), 256>>>(pattn, pqkv, pao);

        launch_tcgemm(2, pao, proj_w + (long long)i * CDIM * CDIM,
                      proj_b + i * CDIM, px, px,
                      MROWS, CDIM, CDIM, CDIM, CDIM, CDIM);

        ln_k<<<MROWS, 128>>>(px, ln2_w + i * CDIM, ln2_b + i * CDIM, phb, 1e-6f);

        launch_tcgemm(1, phb, fc1_w + (long long)i * FFDIM * CDIM,
                      fc1_b + i * FFDIM, nullptr, pffn,
                      MROWS, FFDIM, CDIM, CDIM, CDIM, FFDIM);

        launch_tcgemm(2, pffn, fc2_w + (long long)i * CDIM * FFDIM,
                      fc2_b + i * CDIM, px, px,
                      MROWS, CDIM, FFDIM, FFDIM, FFDIM, CDIM);
    }

    {
        long long total = (long long)BATCH * CDIM * NSP + (long long)BATCH * CDIM;
        int blocks = (int)((total + 255) / 256);
        final_k<<<blocks, 256>>>(px, (float*)d_out);
    }
}

// round 5
// speedup vs baseline: 3.4809x; 1.2389x over previous
#include <cuda_runtime.h>
#include <cuda_fp16.h>
#include <math.h>
#include <stdint.h>

#define DEPTHN 12
#define BATCH 128
#define NTOK 197
#define NSP 196
#define CDIM 384
#define NHEAD 6
#define HDIM 64
#define MROWS (BATCH*NTOK)      /* 25216 */
#define FFDIM 1536
#define QKVDIM 1152
#define ASTRIDE 224             /* padded attention row stride */

/* per-layer packed half-weight layout */
#define W_QKV_OFF 0
#define W_PROJ_OFF 442368
#define W_FC1_OFF 589824
#define W_FC2_OFF 1179648
#define LW 1769472

/* ---------------- scratch (device globals; zero-initialized) ------------- */
__device__ float  g_x   [MROWS*CDIM];
__device__ float  g_attn[(long long)BATCH*NHEAD*ASTRIDE*ASTRIDE]; /* zero pads persist */
__device__ __half g_h16 [MROWS*CDIM];
__device__ __half g_qkv16[MROWS*QKVDIM];
__device__ __half g_ao16[MROWS*CDIM];
__device__ __half g_ffn16[(long long)MROWS*FFDIM];
__device__ __half g_wh  [(long long)DEPTHN*LW];
__device__ float  g_pol [BATCH*NTOK];
__device__ float  g_ph  [BATCH*NSP*NHEAD*HDIM];
__device__ float  g_glob[BATCH*NHEAD*32];
__device__ float  g_den [BATCH];

__device__ __forceinline__ float gelu_f(float x) {
    return 0.5f * x * (1.0f + erff(x * 0.70710678118654752440f));
}

__device__ __forceinline__ uint32_t smem_u32(const void* p) {
    uint32_t a;
    asm("{ .reg .u64 t; cvta.to.shared.u64 t, %1; cvt.u32.u64 %0, t; }" : "=r"(a) : "l"(p));
    return a;
}

__device__ __forceinline__ uint32_t pack_h2(float lo, float hi) {
    uint32_t r;
    asm("cvt.rn.f16x2.f32 %0, %1, %2;" : "=r"(r) : "f"(hi), "f"(lo));
    return r;
}

__device__ __forceinline__ void cp_async16(uint32_t saddr, const void* g) {
    asm volatile("cp.async.cg.shared.global [%0], [%1], 16;" :: "r"(saddr), "l"(g));
}
#define CP_COMMIT() asm volatile("cp.async.commit_group;" ::: "memory")
#define CP_WAIT(n)  asm volatile("cp.async.wait_group %0;" :: "n"(n) : "memory")

__device__ __forceinline__ void mma_f16(
    float& d0, float& d1, float& d2, float& d3,
    uint32_t a0, uint32_t a1, uint32_t a2, uint32_t a3,
    uint32_t b0, uint32_t b1)
{
    asm volatile(
        "mma.sync.aligned.m16n8k16.row.col.f32.f16.f16.f32 "
        "{%0,%1,%2,%3}, {%4,%5,%6,%7}, {%8,%9}, {%0,%1,%2,%3};"
        : "+f"(d0), "+f"(d1), "+f"(d2), "+f"(d3)
        : "r"(a0), "r"(a1), "r"(a2), "r"(a3), "r"(b0), "r"(b1));
}

/* ---------------- weight fp32 -> fp16 (strided per layer) ---------------- */
__global__ void cvtw_k(const float* __restrict__ src, __half* __restrict__ dstbase,
                       int perL, int off, long long total)
{
    long long i = (long long)blockIdx.x * blockDim.x + threadIdx.x;
    if (i < total) {
        int l = (int)(i / perL);
        int r = (int)(i % perL);
        dstbase[(long long)l * LW + off + r] = __float2half(src[i]);
    }
}

/* ================= dense fp16 HMMA GEMM (cp.async, BK=64, 2-stage) ======
 * C[m,n] = sum_k A[m,k]*B[n,k] + bias[n]   (EPI: 0 none, 1 gelu, 2 +R)
 * A,B fp16; C fp16 (OUTH) or fp32. M%128==0, N%128==0, K%64==0.
 * 256 threads, 8 warps (2M x 4N), warp 64x32.
 * dyn smem: 2 stages x 128x72 halfs x 2 matrices = 73728 B.
 */
#define DENSE_SMEM 73728

template<int EPI, bool OUTH>
__global__ void __launch_bounds__(256, 2)
hgemm_k(const __half* __restrict__ A, const __half* __restrict__ B,
        const float* __restrict__ bias, const float* __restrict__ R,
        void* __restrict__ Cv, int K, int lda, int ldb, int ldc)
{
    extern __shared__ __half hsm[];
    __half* As = hsm;              /* [2][128*72] */
    __half* Bs = hsm + 18432;
    const uint32_t asb = smem_u32(As), bsb = smem_u32(Bs);

    const int tid = threadIdx.x, wid = tid >> 5, lane = tid & 31;
    const int lane4 = lane >> 2, lanek = lane & 3;
    const int warpM = wid & 1, warpN = wid >> 1;
    const int m0 = blockIdx.y * 128, n0 = blockIdx.x * 128;

    float acc[4][4][4];
    #pragma unroll
    for (int i = 0; i < 4; i++)
        #pragma unroll
        for (int j = 0; j < 4; j++)
            #pragma unroll
            for (int r = 0; r < 4; r++) acc[i][j][r] = 0.f;

#define HISSUE(t_, s_) do {                                                     \
    int k0_ = (t_) * 64;                                                        \
    _Pragma("unroll")                                                           \
    for (int i_ = 0; i_ < 4; i_++) {                                            \
        int idx_ = tid + 256 * i_;                                              \
        int row_ = idx_ >> 3, ch_ = idx_ & 7;                                   \
        uint32_t so_ = (uint32_t)(((s_) * 9216 + row_ * 72 + ch_ * 8) * 2);     \
        cp_async16(asb + so_, A + (size_t)(m0 + row_) * lda + k0_ + ch_ * 8);   \
        cp_async16(bsb + so_, B + (size_t)(n0 + row_) * ldb + k0_ + ch_ * 8);   \
    }                                                                           \
    CP_COMMIT();                                                                \
} while (0)

    const int T = K >> 6;
    HISSUE(0, 0);

    for (int t = 0; t < T; t++) {
        int p = t & 1;
        if (t + 1 < T) { HISSUE(t + 1, p ^ 1); CP_WAIT(1); }
        else           { CP_WAIT(0); }
        __syncthreads();

        const __half* Ap = As + p * 9216;
        const __half* Bp = Bs + p * 9216;
        #pragma unroll
        for (int ks = 0; ks < 4; ks++) {
            const int kk = ks * 16 + lanek * 2;
            uint32_t a[4][4], b[4][2];
            #pragma unroll
            for (int mf = 0; mf < 4; mf++) {
                int rb = warpM * 64 + mf * 16 + lane4;
                a[mf][0] = *(const uint32_t*)(Ap + rb * 72 + kk);
                a[mf][1] = *(const uint32_t*)(Ap + (rb + 8) * 72 + kk);
                a[mf][2] = *(const uint32_t*)(Ap + rb * 72 + kk + 8);
                a[mf][3] = *(const uint32_t*)(Ap + (rb + 8) * 72 + kk + 8);
            }
            #pragma unroll
            for (int nf = 0; nf < 4; nf++) {
                int nb = warpN * 32 + nf * 8 + lane4;
                b[nf][0] = *(const uint32_t*)(Bp + nb * 72 + kk);
                b[nf][1] = *(const uint32_t*)(Bp + nb * 72 + kk + 8);
            }
            #pragma unroll
            for (int mf = 0; mf < 4; mf++)
                #pragma unroll
                for (int nf = 0; nf < 4; nf++)
                    mma_f16(acc[mf][nf][0], acc[mf][nf][1],
                            acc[mf][nf][2], acc[mf][nf][3],
                            a[mf][0], a[mf][1], a[mf][2], a[mf][3],
                            b[nf][0], b[nf][1]);
        }
        if (t + 1 < T) __syncthreads();
    }
#undef HISSUE

    /* epilogue */
    #pragma unroll
    for (int mf = 0; mf < 4; mf++) {
        int m = m0 + warpM * 64 + mf * 16 + lane4;
        #pragma unroll
        for (int nf = 0; nf < 4; nf++) {
            int n = n0 + warpN * 32 + nf * 8 + lanek * 2;
            float bz0 = bias ? __ldg(bias + n)     : 0.f;
            float bz1 = bias ? __ldg(bias + n + 1) : 0.f;
            size_t gi0 = (size_t)m * ldc + n;
            size_t gi1 = (size_t)(m + 8) * ldc + n;
            float v0 = acc[mf][nf][0] + bz0;
            float v1 = acc[mf][nf][1] + bz1;
            float v2 = acc[mf][nf][2] + bz0;
            float v3 = acc[mf][nf][3] + bz1;
            if (EPI == 1) {
                v0 = gelu_f(v0); v1 = gelu_f(v1);
                v2 = gelu_f(v2); v3 = gelu_f(v3);
            } else if (EPI == 2) {
                v0 += R[gi0]; v1 += R[gi0 + 1];
                v2 += R[gi1]; v3 += R[gi1 + 1];
            }
            if (OUTH) {
                __half* C = (__half*)Cv;
                *(__half2*)(C + gi0) = __floats2half2_rn(v0, v1);
                *(__half2*)(C + gi1) = __floats2half2_rn(v2, v3);
            } else {
                float* C = (float*)Cv;
                *(float2*)(C + gi0) = make_float2(v0, v1);
                *(float2*)(C + gi1) = make_float2(v2, v3);
            }
        }
    }
}

/* ================= attention scores: S = Q @ K^T * 0.125 (fp16 HMMA) ====
 * per (b,h): [197,64] @ [197,64]^T -> fp32 [197,197] (row stride 224).
 * grid (2,2,768), 256 threads. static smem 36864 B.
 */
__global__ void __launch_bounds__(256)
score_k(const __half* __restrict__ qkv, float* __restrict__ attn)
{
    __shared__ __half Qs[128 * 72];
    __shared__ __half Ks[128 * 72];

    const int tid = threadIdx.x, wid = tid >> 5, lane = tid & 31;
    const int lane4 = lane >> 2, lanek = lane & 3;
    const int warpM = wid & 1, warpN = wid >> 1;
    const int bh = blockIdx.z, b = bh / NHEAD, h = bh % NHEAD;
    const int m0 = blockIdx.y * 128, n0 = blockIdx.x * 128;

    const __half* qb = qkv + (size_t)b * NTOK * QKVDIM + h * HDIM;
    const __half* kb = qb + CDIM;

    const uint4 zero4 = make_uint4(0, 0, 0, 0);
    #pragma unroll
    for (int p = 0; p < 2; p++) {
        int row = (tid >> 2) + p * 64;
        int col = (tid & 3) * 16;
        uint4 vq0 = zero4, vq1 = zero4, vk0 = zero4, vk1 = zero4;
        if (m0 + row < NTOK) {
            const __half* s = qb + (size_t)(m0 + row) * QKVDIM + col;
            vq0 = *(const uint4*)s; vq1 = *(const uint4*)(s + 8);
        }
        if (n0 + row < NTOK) {
            const __half* s = kb + (size_t)(n0 + row) * QKVDIM + col;
            vk0 = *(const uint4*)s; vk1 = *(const uint4*)(s + 8);
        }
        *(uint4*)&Qs[row * 72 + col]     = vq0;
        *(uint4*)&Qs[row * 72 + col + 8] = vq1;
        *(uint4*)&Ks[row * 72 + col]     = vk0;
        *(uint4*)&Ks[row * 72 + col + 8] = vk1;
    }
    __syncthreads();

    float acc[4][4][4];
    #pragma unroll
    for (int i = 0; i < 4; i++)
        #pragma unroll
        for (int j = 0; j < 4; j++)
            #pragma unroll
            for (int r = 0; r < 4; r++) acc[i][j][r] = 0.f;

    #pragma unroll
    for (int ks = 0; ks < 4; ks++) {
        const int kk = ks * 16 + lanek * 2;
        uint32_t a[4][4], bb[4][2];
        #pragma unroll
        for (int mf = 0; mf < 4; mf++) {
            int rb = warpM * 64 + mf * 16 + lane4;
            a[mf][0] = *(const uint32_t*)(Qs + rb * 72 + kk);
            a[mf][1] = *(const uint32_t*)(Qs + (rb + 8) * 72 + kk);
            a[mf][2] = *(const uint32_t*)(Qs + rb * 72 + kk + 8);
            a[mf][3] = *(const uint32_t*)(Qs + (rb + 8) * 72 + kk + 8);
        }
        #pragma unroll
        for (int nf = 0; nf < 4; nf++) {
            int nb = warpN * 32 + nf * 8 + lane4;
            bb[nf][0] = *(const uint32_t*)(Ks + nb * 72 + kk);
            bb[nf][1] = *(const uint32_t*)(Ks + nb * 72 + kk + 8);
        }
        #pragma unroll
        for (int mf = 0; mf < 4; mf++)
            #pragma unroll
            for (int nf = 0; nf < 4; nf++)
                mma_f16(acc[mf][nf][0], acc[mf][nf][1],
                        acc[mf][nf][2], acc[mf][nf][3],
                        a[mf][0], a[mf][1], a[mf][2], a[mf][3],
                        bb[nf][0], bb[nf][1]);
    }

    float* ab = attn + (size_t)bh * ASTRIDE * ASTRIDE;
    #pragma unroll
    for (int mf = 0; mf < 4; mf++) {
        int m = m0 + warpM * 64 + mf * 16 + lane4;
        #pragma unroll
        for (int nf = 0; nf < 4; nf++) {
            int n = n0 + warpN * 32 + nf * 8 + lanek * 2;
            if (m < NTOK) {
                if (n < NTOK)     ab[(size_t)m * ASTRIDE + n]     = 0.125f * acc[mf][nf][0];
                if (n + 1 < NTOK) ab[(size_t)m * ASTRIDE + n + 1] = 0.125f * acc[mf][nf][1];
            }
            if (m + 8 < NTOK) {
                if (n < NTOK)     ab[(size_t)(m + 8) * ASTRIDE + n]     = 0.125f * acc[mf][nf][2];
                if (n + 1 < NTOK) ab[(size_t)(m + 8) * ASTRIDE + n + 1] = 0.125f * acc[mf][nf][3];
            }
        }
    }
}

/* ================= AV: O = P @ V (fp16 HMMA) ============================
 * per (b,h): fp32 P [197,224pad] x fp16 V [197,64] -> fp16 O in [B,N,H,HD].
 * grid (1,2,768), 256 threads, 8 warps (4M x 2N), warp 32x32.
 */
__global__ void __launch_bounds__(256)
av_k(const float* __restrict__ attn, const __half* __restrict__ qkv,
     __half* __restrict__ ao)
{
    __shared__ __half As[128 * 40];
    __shared__ __half Vs[64 * 40];

    const int tid = threadIdx.x, wid = tid >> 5, lane = tid & 31;
    const int lane4 = lane >> 2, lanek = lane & 3;
    const int warpM = wid >> 1, warpN = wid & 1;
    const int bh = blockIdx.z, b = bh / NHEAD, h = bh % NHEAD;
    const int m0 = blockIdx.y * 128;

    const float* ab = attn + (size_t)bh * ASTRIDE * ASTRIDE;
    const __half* vb = qkv + (size_t)b * NTOK * QKVDIM + h * HDIM + 2 * CDIM;

    float acc[2][4][4];
    #pragma unroll
    for (int i = 0; i < 2; i++)
        #pragma unroll
        for (int j = 0; j < 4; j++)
            #pragma unroll
            for (int r = 0; r < 4; r++) acc[i][j][r] = 0.f;

    for (int t = 0; t < 7; t++) {
        const int k0 = t * 32;
        #pragma unroll
        for (int p = 0; p < 2; p++) {
            int row = (tid >> 2) + p * 64;
            int m = m0 + row;
            int colf = (tid & 3) * 8;
            float4 x = make_float4(0.f, 0.f, 0.f, 0.f);
            float4 y = make_float4(0.f, 0.f, 0.f, 0.f);
            if (m < NTOK) {
                x = *(const float4*)(ab + (size_t)m * ASTRIDE + k0 + colf);
                y = *(const float4*)(ab + (size_t)m * ASTRIDE + k0 + colf + 4);
            }
            uint4 u;
            u.x = pack_h2(x.x, x.y); u.y = pack_h2(x.z, x.w);
            u.z = pack_h2(y.x, y.y); u.w = pack_h2(y.z, y.w);
            *(uint4*)&As[row * 40 + colf] = u;
        }
        {
            int n = tid & 63;
            #pragma unroll
            for (int i = 0; i < 8; i++) {
                int kk = (tid >> 6) + 4 * i;
                int kg = k0 + kk;
                __half v = (kg < NTOK) ? vb[(size_t)kg * QKVDIM + n] : __half(0.f);
                Vs[n * 40 + kk] = v;
            }
        }
        __syncthreads();

        #pragma unroll
        for (int ks = 0; ks < 2; ks++) {
            const int kk = ks * 16 + lanek * 2;
            uint32_t a[2][4], bb[4][2];
            #pragma unroll
            for (int mf = 0; mf < 2; mf++) {
                int rb = warpM * 32 + mf * 16 + lane4;
                a[mf][0] = *(const uint32_t*)(As + rb * 40 + kk);
                a[mf][1] = *(const uint32_t*)(As + (rb + 8) * 40 + kk);
                a[mf][2] = *(const uint32_t*)(As + rb * 40 + kk + 8);
                a[mf][3] = *(const uint32_t*)(As + (rb + 8) * 40 + kk + 8);
            }
            #pragma unroll
            for (int nf = 0; nf < 4; nf++) {
                int nb = warpN * 32 + nf * 8 + lane4;
                bb[nf][0] = *(const uint32_t*)(Vs + nb * 40 + kk);
                bb[nf][1] = *(const uint32_t*)(Vs + nb * 40 + kk + 8);
            }
            #pragma unroll
            for (int mf = 0; mf < 2; mf++)
                #pragma unroll
                for (int nf = 0; nf < 4; nf++)
                    mma_f16(acc[mf][nf][0], acc[mf][nf][1],
                            acc[mf][nf][2], acc[mf][nf][3],
                            a[mf][0], a[mf][1], a[mf][2], a[mf][3],
                            bb[nf][0], bb[nf][1]);
        }
        __syncthreads();
    }

    #pragma unroll
    for (int mf = 0; mf < 2; mf++) {
        int m = m0 + warpM * 32 + mf * 16 + lane4;
        #pragma unroll
        for (int nf = 0; nf < 4; nf++) {
            int n = warpN * 32 + nf * 8 + lanek * 2;
            if (m < NTOK)
                *(__half2*)(ao + (size_t)(b * NTOK + m) * CDIM + h * HDIM + n) =
                    __floats2half2_rn(acc[mf][nf][0], acc[mf][nf][1]);
            if (m + 8 < NTOK)
                *(__half2*)(ao + (size_t)(b * NTOK + m + 8) * CDIM + h * HDIM + n) =
                    __floats2half2_rn(acc[mf][nf][2], acc[mf][nf][3]);
        }
    }
}

/* ---------------- block reductions --------------------------------------- */
__device__ __forceinline__ float blockReduceSum(float v, float* sh) {
    int tid = threadIdx.x, lane = tid & 31, w = tid >> 5;
    #pragma unroll
    for (int o = 16; o; o >>= 1) v += __shfl_xor_sync(0xffffffffu, v, o);
    if (lane == 0) sh[w] = v;
    __syncthreads();
    int nw = (blockDim.x + 31) >> 5;
    v = (tid < nw) ? sh[tid] : 0.f;
    if (w == 0) {
        #pragma unroll
        for (int o = 16; o; o >>= 1) v += __shfl_xor_sync(0xffffffffu, v, o);
        if (lane == 0) sh[0] = v;
    }
    __syncthreads();
    float r = sh[0];
    __syncthreads();
    return r;
}

/* ---------------- warp-per-row policy softmax ----------------------------- */
__global__ void __launch_bounds__(256)
softmax_pol_k(float* __restrict__ attn, const float* __restrict__ pol)
{
    int wid = threadIdx.x >> 5, lane = threadIdx.x & 31;
    long long r = (long long)blockIdx.x * 8 + wid;
    int bh = (int)(r / NTOK), n = (int)(r % NTOK);
    int b = bh / NHEAD;
    float* row = attn + ((size_t)bh * ASTRIDE + n) * ASTRIDE;
    const float* pb = pol + b * NTOK;

    float v[7];
    float mx = -1e30f;
    #pragma unroll
    for (int i = 0; i < 7; i++) {
        int m = lane + 32 * i;
        v[i] = (m < NTOK) ? row[m] : -1e30f;
        mx = fmaxf(mx, v[i]);
    }
    #pragma unroll
    for (int o = 16; o; o >>= 1) mx = fmaxf(mx, __shfl_xor_sync(0xffffffffu, mx, o));

    float sum = 0.f;
    #pragma unroll
    for (int i = 0; i < 7; i++) {
        int m = lane + 32 * i;
        if (m < NTOK) {
            float ap = (m == n) ? 1.0f : pb[m];
            float e = expf(v[i] - mx) * ap;
            v[i] = e;
            sum += e;
        }
    }
    #pragma unroll
    for (int o = 16; o; o >>= 1) sum += __shfl_xor_sync(0xffffffffu, sum, o);
    float inv = 1.0f / sum;
    #pragma unroll
    for (int i = 0; i < 7; i++) {
        int m = lane + 32 * i;
        if (m < NTOK) row[m] = v[i] * inv;
    }
}

/* ---------------- LayerNorm over C=384 -> fp16 out ------------------------ */
__global__ void ln_k(const float* __restrict__ x, const float* __restrict__ w,
                     const float* __restrict__ bb, __half* __restrict__ out, float eps)
{
    __shared__ float sh[32];
    long long row = blockIdx.x;
    const float* xr = x + row * CDIM;
    int tid = threadIdx.x; /* 128 */
    float v0 = xr[tid], v1 = xr[tid + 128], v2 = xr[tid + 256];
    float s = blockReduceSum(v0 + v1 + v2, sh);
    float m = s * (1.f / 384.f);
    float d0 = v0 - m, d1 = v1 - m, d2 = v2 - m;
    float q = blockReduceSum(d0*d0 + d1*d1 + d2*d2, sh);
    float rs = rsqrtf(q * (1.f / 384.f) + eps);
    __half* orow = out + row * CDIM;
    orow[tid]       = __float2half(d0 * rs * w[tid]       + bb[tid]);
    orow[tid + 128] = __float2half(d1 * rs * w[tid + 128] + bb[tid + 128]);
    orow[tid + 256] = __float2half(d2 * rs * w[tid + 256] + bb[tid + 256]);
}

/* ---------------- init / final ------------------------------------------- */
__global__ void init_x_k(const float* __restrict__ xin, const float* __restrict__ cls,
                         const float* __restrict__ polin,
                         float* __restrict__ x, float* __restrict__ pol)
{
    long long idx = (long long)blockIdx.x * blockDim.x + threadIdx.x;
    long long total = (long long)MROWS * CDIM;
    if (idx < total) {
        int c  = (int)(idx % CDIM);
        int nn = (int)((idx / CDIM) % NTOK);
        int b  = (int)(idx / ((long long)CDIM * NTOK));
        float v;
        if (nn == 0) v = cls[b * CDIM + c];
        else         v = xin[((long long)b * CDIM + c) * NSP + (nn - 1)];
        x[idx] = v;
    }
    if (idx < BATCH * NTOK) pol[idx] = polin[idx];
}

__global__ void final_k(const float* __restrict__ x, float* __restrict__ out)
{
    long long idx = (long long)blockIdx.x * blockDim.x + threadIdx.x;
    const long long total_sp = (long long)BATCH * CDIM * NSP;
    if (idx < total_sp) {
        int hw = (int)(idx % NSP);
        int c  = (int)((idx / NSP) % CDIM);
        int b  = (int)(idx / ((long long)NSP * CDIM));
        out[idx] = x[((long long)(b * NTOK) + 1 + hw) * CDIM + c];
    } else if (idx < total_sp + (long long)BATCH * CDIM) {
        long long rr = idx - total_sp;
        int c = (int)(rr % CDIM);
        int b = (int)(rr / CDIM);
        out[idx] = x[((long long)b * NTOK) * CDIM + c];
    }
}

/* ---------------- predictor --------------------------------------------- */
__global__ void den_k(const float* __restrict__ pol, float* __restrict__ den)
{
    __shared__ float sh[32];
    int b = blockIdx.x;
    int tid = threadIdx.x;
    float v = (tid < NSP) ? pol[b * NTOK + 1 + tid] : 0.f;
    float s = blockReduceSum(v, sh);
    if (tid == 0) den[b] = s;
}

__global__ void p1_k(const float* __restrict__ x,
                     const float* __restrict__ lnw, const float* __restrict__ lnb,
                     const float* __restrict__ Win, const float* __restrict__ bin,
                     float* __restrict__ ph)
{
    int bn = blockIdx.x;
    int b = bn / NSP, n = bn % NSP;
    int wid = threadIdx.x >> 5, lane = threadIdx.x & 31;
    __shared__ float sh[NHEAD][HDIM];

    const float* xr = x + ((long long)(b * NTOK + 1 + n)) * CDIM + wid * HDIM;
    float v0 = xr[lane], v1 = xr[lane + 32];
    float s = v0 + v1;
    #pragma unroll
    for (int o = 16; o; o >>= 1) s += __shfl_xor_sync(0xffffffffu, s, o);
    float m = s * (1.f / 64.f);
    float d0 = v0 - m, d1 = v1 - m;
    float q = d0*d0 + d1*d1;
    #pragma unroll
    for (int o = 16; o; o >>= 1) q += __shfl_xor_sync(0xffffffffu, q, o);
    float rs = rsqrtf(q * (1.f / 64.f) + 1e-5f);
    sh[wid][lane]      = d0 * rs * lnw[lane]      + lnb[lane];
    sh[wid][lane + 32] = d1 * rs * lnw[lane + 32] + lnb[lane + 32];
    __syncwarp();

    float a0 = bin[lane], a1 = bin[lane + 32];
    const float* w0 = Win + lane * 64;
    const float* w1 = Win + (lane + 32) * 64;
    #pragma unroll 8
    for (int e = 0; e < 64; e++) {
        float he = sh[wid][e];
        a0 += w0[e] * he;
        a1 += w1[e] * he;
    }
    float* o = ph + ((long long)bn * NHEAD + wid) * HDIM;
    o[lane]      = gelu_f(a0);
    o[lane + 32] = gelu_f(a1);
}

__global__ void p2_k(const float* __restrict__ ph, const float* __restrict__ pol,
                     const float* __restrict__ den, float* __restrict__ glob)
{
    int bh = blockIdx.x;
    int b = bh / NHEAD, h = bh % NHEAD;
    int tid = threadIdx.x;
    int d = tid & 31, seg = tid >> 5;
    float s = 0.f;
    for (int n = seg; n < NSP; n += 8)
        s += ph[(((long long)(b * NSP + n)) * NHEAD + h) * HDIM + 32 + d]
             * pol[b * NTOK + 1 + n];
    __shared__ float sh[8][32];
    sh[seg][d] = s;
    __syncthreads();
    if (seg == 0) {
        float t = 0.f;
        #pragma unroll
        for (int k = 0; k < 8; k++) t += sh[k][d];
        glob[(b * NHEAD + h) * 32 + d] = t / den[b];
    }
}

__global__ void p3_k(const float* __restrict__ ph, const float* __restrict__ glob,
                     const float* __restrict__ W1, const float* __restrict__ b1,
                     const float* __restrict__ W2, const float* __restrict__ b2,
                     const float* __restrict__ W3, const float* __restrict__ b3,
                     const float* __restrict__ gum, float* __restrict__ pol)
{
    int bn = blockIdx.x;
    int b = bn / NSP, n = bn % NSP;
    int wid = threadIdx.x >> 5, lane = threadIdx.x & 31;
    __shared__ float h2[NHEAD][64];
    __shared__ float o1[NHEAD][32];
    __shared__ float o2[NHEAD][16];
    __shared__ float zz[NHEAD][2];

    const float* hin = ph + ((long long)bn * NHEAD + wid) * HDIM;
    h2[wid][lane]      = hin[lane];
    h2[wid][32 + lane] = glob[(b * NHEAD + wid) * 32 + lane];
    __syncwarp();
    {
        float a = b1[lane];
        const float* wr = W1 + lane * 64;
        #pragma unroll 8
        for (int e = 0; e < 64; e++) a += wr[e] * h2[wid][e];
        o1[wid][lane] = gelu_f(a);
    }
    __syncwarp();
    if (lane < 16) {
        float a = b2[lane];
        const float* wr = W2 + lane * 32;
        #pragma unroll 8
        for (int e = 0; e < 32; e++) a += wr[e] * o1[wid][e];
        o2[wid][lane] = gelu_f(a);
    }
    __syncwarp();
    if (lane < 2) {
        float a = b3[lane];
        const float* wr = W3 + lane * 16;
        #pragma unroll
        for (int e = 0; e < 16; e++) a += wr[e] * o2[wid][e];
        zz[wid][lane] = a;
    }
    __syncthreads();
    if (threadIdx.x == 0) {
        float s0 = 0.f, s1 = 0.f;
        #pragma unroll
        for (int h = 0; h < NHEAD; h++) {
            float z0 = zz[h][0], z1 = zz[h][1];
            float mx = fmaxf(z0, z1);
            float lse = mx + logf(expf(z0 - mx) + expf(z1 - mx));
            s0 += z0 - lse;
            s1 += z1 - lse;
        }
        s0 *= (1.f / 6.f); s1 *= (1.f / 6.f);
        float u0 = gum[((long long)b * NSP + n) * 2 + 0];
        float u1 = gum[((long long)b * NSP + n) * 2 + 1];
        float g0 = -logf(-logf(u0 + 1e-10f) + 1e-10f);
        float g1 = -logf(-logf(u1 + 1e-10f) + 1e-10f);
        int idx = b * NTOK + 1 + n;
        float keep = (s0 + g0 >= s1 + g1) ? pol[idx] : 0.f;
        pol[idx] = keep;
    }
}

/* ---------------- host-side ------------------------------------------------ */
extern "C" void kernel_launch(void* const* d_in, const int* in_sizes, int n_in,
                              void* d_out, int out_size)
{
    const float* in_x     = (const float*)d_in[0];
    const float* in_cls   = (const float*)d_in[1];
    const float* in_pol   = (const float*)d_in[2];
    const float* in_gum   = (const float*)d_in[3];
    const float* ln1_w    = (const float*)d_in[4];
    const float* ln1_b    = (const float*)d_in[5];
    const float* qkv_w    = (const float*)d_in[6];
    const float* qkv_b    = (const float*)d_in[7];
    const float* proj_w   = (const float*)d_in[8];
    const float* proj_b   = (const float*)d_in[9];
    const float* ln2_w    = (const float*)d_in[10];
    const float* ln2_b    = (const float*)d_in[11];
    const float* fc1_w    = (const float*)d_in[12];
    const float* fc1_b    = (const float*)d_in[13];
    const float* fc2_w    = (const float*)d_in[14];
    const float* fc2_b    = (const float*)d_in[15];
    const float* p_ln_w   = (const float*)d_in[16];
    const float* p_ln_b   = (const float*)d_in[17];
    const float* p_in_w   = (const float*)d_in[18];
    const float* p_in_b   = (const float*)d_in[19];
    const float* p_o1_w   = (const float*)d_in[20];
    const float* p_o1_b   = (const float*)d_in[21];
    const float* p_o2_w   = (const float*)d_in[22];
    const float* p_o2_b   = (const float*)d_in[23];
    const float* p_o3_w   = (const float*)d_in[24];
    const float* p_o3_b   = (const float*)d_in[25];

    cudaFuncSetAttribute(hgemm_k<0, true >, cudaFuncAttributeMaxDynamicSharedMemorySize, DENSE_SMEM);
    cudaFuncSetAttribute(hgemm_k<1, true >, cudaFuncAttributeMaxDynamicSharedMemorySize, DENSE_SMEM);
    cudaFuncSetAttribute(hgemm_k<2, false>, cudaFuncAttributeMaxDynamicSharedMemorySize, DENSE_SMEM);

    float  *px, *pattn, *ppol, *pph, *pglob, *pden;
    __half *ph16, *pqkv16, *pao16, *pffn16, *pwh;
    cudaGetSymbolAddress((void**)&px,     g_x);
    cudaGetSymbolAddress((void**)&pattn,  g_attn);
    cudaGetSymbolAddress((void**)&ph16,   g_h16);
    cudaGetSymbolAddress((void**)&pqkv16, g_qkv16);
    cudaGetSymbolAddress((void**)&pao16,  g_ao16);
    cudaGetSymbolAddress((void**)&pffn16, g_ffn16);
    cudaGetSymbolAddress((void**)&pwh,    g_wh);
    cudaGetSymbolAddress((void**)&ppol,   g_pol);
    cudaGetSymbolAddress((void**)&pph,    g_ph);
    cudaGetSymbolAddress((void**)&pglob,  g_glob);
    cudaGetSymbolAddress((void**)&pden,   g_den);

    /* weights fp32 -> fp16 scratch (per-layer packed) */
    {
        long long nq = (long long)DEPTHN * QKVDIM * CDIM;
        long long np = (long long)DEPTHN * CDIM * CDIM;
        long long n1 = (long long)DEPTHN * FFDIM * CDIM;
        long long n2 = (long long)DEPTHN * CDIM * FFDIM;
        cvtw_k<<<(int)((nq + 255) / 256), 256>>>(qkv_w,  pwh, QKVDIM * CDIM, W_QKV_OFF,  nq);
        cvtw_k<<<(int)((np + 255) / 256), 256>>>(proj_w, pwh, CDIM * CDIM,   W_PROJ_OFF, np);
        cvtw_k<<<(int)((n1 + 255) / 256), 256>>>(fc1_w,  pwh, FFDIM * CDIM,  W_FC1_OFF,  n1);
        cvtw_k<<<(int)((n2 + 255) / 256), 256>>>(fc2_w,  pwh, CDIM * FFDIM,  W_FC2_OFF,  n2);
    }

    {
        long long total = (long long)MROWS * CDIM;
        int blocks = (int)((total + 255) / 256);
        init_x_k<<<blocks, 256>>>(in_x, in_cls, in_pol, px, ppol);
    }

    int pc = 0;
    for (int i = 0; i < DEPTHN; i++) {
        const __half* wl = pwh + (long long)i * LW;
        if (i == 3 || i == 6 || i == 9) {
            den_k<<<BATCH, 256>>>(ppol, pden);
            p1_k<<<BATCH * NSP, 192>>>(px,
                p_ln_w + pc * HDIM, p_ln_b + pc * HDIM,
                p_in_w + pc * HDIM * HDIM, p_in_b + pc * HDIM, pph);
            p2_k<<<BATCH * NHEAD, 256>>>(pph, ppol, pden, pglob);
            p3_k<<<BATCH * NSP, 192>>>(pph, pglob,
                p_o1_w + pc * 32 * 64, p_o1_b + pc * 32,
                p_o2_w + pc * 16 * 32, p_o2_b + pc * 16,
                p_o3_w + pc * 2 * 16,  p_o3_b + pc * 2,
                in_gum + (long long)pc * BATCH * NSP * 2, ppol);
            pc++;
        }

        ln_k<<<MROWS, 128>>>(px, ln1_w + i * CDIM, ln1_b + i * CDIM, ph16, 1e-6f);

        /* qkv: fp16 out */
        hgemm_k<0, true><<<dim3(QKVDIM / 128, MROWS / 128), 256, DENSE_SMEM>>>(
            ph16, wl + W_QKV_OFF, qkv_b + i * QKVDIM, nullptr, pqkv16,
            CDIM, CDIM, CDIM, QKVDIM);

        score_k<<<dim3(2, 2, BATCH * NHEAD), 256>>>(pqkv16, pattn);

        softmax_pol_k<<<(BATCH * NHEAD * NTOK) / 8, 256>>>(pattn, ppol);

        av_k<<<dim3(1, 2, BATCH * NHEAD), 256>>>(pattn, pqkv16, pao16);

        /* proj + residual: fp32 out into px */
        hgemm_k<2, false><<<dim3(CDIM / 128, MROWS / 128), 256, DENSE_SMEM>>>(
            pao16, wl + W_PROJ_OFF, proj_b + i * CDIM, px, px,
            CDIM, CDIM, CDIM, CDIM);

        ln_k<<<MROWS, 128>>>(px, ln2_w + i * CDIM, ln2_b + i * CDIM, ph16, 1e-6f);

        /* fc1 + gelu: fp16 out */
        hgemm_k<1, true><<<dim3(FFDIM / 128, MROWS / 128), 256, DENSE_SMEM>>>(
            ph16, wl + W_FC1_OFF, fc1_b + i * FFDIM, nullptr, pffn16,
            CDIM, CDIM, CDIM, FFDIM);

        /* fc2 + residual: fp32 out */
        hgemm_k<2, false><<<dim3(CDIM / 128, MROWS / 128), 256, DENSE_SMEM>>>(
            pffn16, wl + W_FC2_OFF, fc2_b + i * CDIM, px, px,
            FFDIM, FFDIM, FFDIM, CDIM);
    }

    {
        long long total = (long long)BATCH * CDIM * NSP + (long long)BATCH * CDIM;
        int blocks = (int)((total + 255) / 256);
        final_k<<<blocks, 256>>>(px, (float*)d_out);
    }
}

// round 6
// speedup vs baseline: 3.6501x; 1.0486x over previous
#include <cuda_runtime.h>
#include <cuda_fp16.h>
#include <math.h>
#include <stdint.h>

#define DEPTHN 12
#define BATCH 128
#define NTOK 197
#define NSP 196
#define CDIM 384
#define NHEAD 6
#define HDIM 64
#define MROWS (BATCH*NTOK)      /* 25216 */
#define FFDIM 1536
#define QKVDIM 1152
#define ASTRIDE 224             /* padded attention row stride */

/* per-layer packed half-weight layout */
#define W_QKV_OFF 0
#define W_PROJ_OFF 442368
#define W_FC1_OFF 589824
#define W_FC2_OFF 1179648
#define LW 1769472

/* ---------------- scratch (device globals; zero-initialized) ------------- */
__device__ float  g_x   [MROWS*CDIM];
__device__ __half g_attn[(long long)BATCH*NHEAD*ASTRIDE*ASTRIDE]; /* zero pads persist */
__device__ __half g_h16 [MROWS*CDIM];
__device__ __half g_qkv16[MROWS*QKVDIM];
__device__ __half g_ao16[MROWS*CDIM];
__device__ __half g_ffn16[(long long)MROWS*FFDIM];
__device__ __half g_wh  [(long long)DEPTHN*LW];
__device__ float  g_pol [BATCH*NTOK];
__device__ float  g_ph  [BATCH*NSP*NHEAD*HDIM];
__device__ float  g_glob[BATCH*NHEAD*32];
__device__ float  g_den [BATCH];

__device__ __forceinline__ float gelu_f(float x) {
    return 0.5f * x * (1.0f + erff(x * 0.70710678118654752440f));
}

__device__ __forceinline__ uint32_t smem_u32(const void* p) {
    uint32_t a;
    asm("{ .reg .u64 t; cvta.to.shared.u64 t, %1; cvt.u32.u64 %0, t; }" : "=r"(a) : "l"(p));
    return a;
}

__device__ __forceinline__ void cp_async16(uint32_t saddr, const void* g) {
    asm volatile("cp.async.cg.shared.global [%0], [%1], 16;" :: "r"(saddr), "l"(g));
}
#define CP_COMMIT() asm volatile("cp.async.commit_group;" ::: "memory")
#define CP_WAIT(n)  asm volatile("cp.async.wait_group %0;" :: "n"(n) : "memory")

__device__ __forceinline__ void ldsm_x4(uint32_t& r0, uint32_t& r1,
                                        uint32_t& r2, uint32_t& r3, uint32_t a) {
    asm volatile("ldmatrix.sync.aligned.m8n8.x4.shared.b16 {%0,%1,%2,%3}, [%4];"
                 : "=r"(r0), "=r"(r1), "=r"(r2), "=r"(r3) : "r"(a));
}
__device__ __forceinline__ void ldsm_x2(uint32_t& r0, uint32_t& r1, uint32_t a) {
    asm volatile("ldmatrix.sync.aligned.m8n8.x2.shared.b16 {%0,%1}, [%2];"
                 : "=r"(r0), "=r"(r1) : "r"(a));
}

__device__ __forceinline__ void mma_f16(
    float& d0, float& d1, float& d2, float& d3,
    uint32_t a0, uint32_t a1, uint32_t a2, uint32_t a3,
    uint32_t b0, uint32_t b1)
{
    asm volatile(
        "mma.sync.aligned.m16n8k16.row.col.f32.f16.f16.f32 "
        "{%0,%1,%2,%3}, {%4,%5,%6,%7}, {%8,%9}, {%0,%1,%2,%3};"
        : "+f"(d0), "+f"(d1), "+f"(d2), "+f"(d3)
        : "r"(a0), "r"(a1), "r"(a2), "r"(a3), "r"(b0), "r"(b1));
}

/* ---------------- weight fp32 -> fp16 (strided per layer) ---------------- */
__global__ void cvtw_k(const float* __restrict__ src, __half* __restrict__ dstbase,
                       int perL, int off, long long total)
{
    long long i = (long long)blockIdx.x * blockDim.x + threadIdx.x;
    if (i < total) {
        int l = (int)(i / perL);
        int r = (int)(i % perL);
        dstbase[(long long)l * LW + off + r] = __float2half(src[i]);
    }
}

/* ================= dense fp16 HMMA GEMM (cp.async, BK=64, 2-stage) ======
 * C[m,n] = sum_k A[m,k]*B[n,k] + bias[n]   (EPI: 0 none, 1 gelu, 2 +R)
 * A,B fp16; C fp16 (OUTH) or fp32. M%128==0, N%128==0, K%64==0.
 * 256 threads, 8 warps (2M x 4N), warp 64x32; ldmatrix fragment loads.
 */
#define DENSE_SMEM 73728

template<int EPI, bool OUTH>
__global__ void __launch_bounds__(256, 2)
hgemm_k(const __half* __restrict__ A, const __half* __restrict__ B,
        const float* __restrict__ bias, const float* __restrict__ R,
        void* __restrict__ Cv, int K, int lda, int ldb, int ldc)
{
    extern __shared__ __half hsm[];
    __half* As = hsm;              /* [2][128*72] */
    __half* Bs = hsm + 18432;
    const uint32_t asb = smem_u32(As), bsb = smem_u32(Bs);

    const int tid = threadIdx.x, wid = tid >> 5, lane = tid & 31;
    const int lane4 = lane >> 2, lanek = lane & 3;
    const int warpM = wid & 1, warpN = wid >> 1;
    const int m0 = blockIdx.y * 128, n0 = blockIdx.x * 128;

    /* ldmatrix lane addressing */
    const int mat = lane >> 3;
    const int arow = (lane & 7) + (mat & 1) * 8;
    const int acol = (mat >> 1) * 8;
    const int brow = lane & 7;
    const int bcol = ((lane >> 3) & 1) * 8;

    float acc[4][4][4];
    #pragma unroll
    for (int i = 0; i < 4; i++)
        #pragma unroll
        for (int j = 0; j < 4; j++)
            #pragma unroll
            for (int r = 0; r < 4; r++) acc[i][j][r] = 0.f;

#define HISSUE(t_, s_) do {                                                     \
    int k0_ = (t_) * 64;                                                        \
    _Pragma("unroll")                                                           \
    for (int i_ = 0; i_ < 4; i_++) {                                            \
        int idx_ = tid + 256 * i_;                                              \
        int row_ = idx_ >> 3, ch_ = idx_ & 7;                                   \
        uint32_t so_ = (uint32_t)(((s_) * 9216 + row_ * 72 + ch_ * 8) * 2);     \
        cp_async16(asb + so_, A + (size_t)(m0 + row_) * lda + k0_ + ch_ * 8);   \
        cp_async16(bsb + so_, B + (size_t)(n0 + row_) * ldb + k0_ + ch_ * 8);   \
    }                                                                           \
    CP_COMMIT();                                                                \
} while (0)

    const int T = K >> 6;
    HISSUE(0, 0);

    for (int t = 0; t < T; t++) {
        int p = t & 1;
        if (t + 1 < T) { HISSUE(t + 1, p ^ 1); CP_WAIT(1); }
        else           { CP_WAIT(0); }
        __syncthreads();

        uint32_t aAddr[4], bAddr[4];
        #pragma unroll
        for (int mf = 0; mf < 4; mf++)
            aAddr[mf] = asb + (uint32_t)((p * 9216 + (warpM * 64 + mf * 16 + arow) * 72 + acol) * 2);
        #pragma unroll
        for (int nf = 0; nf < 4; nf++)
            bAddr[nf] = bsb + (uint32_t)((p * 9216 + (warpN * 32 + nf * 8 + brow) * 72 + bcol) * 2);

        #pragma unroll
        for (int ks = 0; ks < 4; ks++) {
            uint32_t a[4][4], b[4][2];
            #pragma unroll
            for (int mf = 0; mf < 4; mf++)
                ldsm_x4(a[mf][0], a[mf][1], a[mf][2], a[mf][3], aAddr[mf] + ks * 32);
            #pragma unroll
            for (int nf = 0; nf < 4; nf++)
                ldsm_x2(b[nf][0], b[nf][1], bAddr[nf] + ks * 32);
            #pragma unroll
            for (int mf = 0; mf < 4; mf++)
                #pragma unroll
                for (int nf = 0; nf < 4; nf++)
                    mma_f16(acc[mf][nf][0], acc[mf][nf][1],
                            acc[mf][nf][2], acc[mf][nf][3],
                            a[mf][0], a[mf][1], a[mf][2], a[mf][3],
                            b[nf][0], b[nf][1]);
        }
        if (t + 1 < T) __syncthreads();
    }
#undef HISSUE

    /* epilogue */
    #pragma unroll
    for (int mf = 0; mf < 4; mf++) {
        int m = m0 + warpM * 64 + mf * 16 + lane4;
        #pragma unroll
        for (int nf = 0; nf < 4; nf++) {
            int n = n0 + warpN * 32 + nf * 8 + lanek * 2;
            float bz0 = bias ? __ldg(bias + n)     : 0.f;
            float bz1 = bias ? __ldg(bias + n + 1) : 0.f;
            size_t gi0 = (size_t)m * ldc + n;
            size_t gi1 = (size_t)(m + 8) * ldc + n;
            float v0 = acc[mf][nf][0] + bz0;
            float v1 = acc[mf][nf][1] + bz1;
            float v2 = acc[mf][nf][2] + bz0;
            float v3 = acc[mf][nf][3] + bz1;
            if (EPI == 1) {
                v0 = gelu_f(v0); v1 = gelu_f(v1);
                v2 = gelu_f(v2); v3 = gelu_f(v3);
            } else if (EPI == 2) {
                v0 += R[gi0]; v1 += R[gi0 + 1];
                v2 += R[gi1]; v3 += R[gi1 + 1];
            }
            if (OUTH) {
                __half* C = (__half*)Cv;
                *(__half2*)(C + gi0) = __floats2half2_rn(v0, v1);
                *(__half2*)(C + gi1) = __floats2half2_rn(v2, v3);
            } else {
                float* C = (float*)Cv;
                *(float2*)(C + gi0) = make_float2(v0, v1);
                *(float2*)(C + gi1) = make_float2(v2, v3);
            }
        }
    }
}

/* ================= attention scores: S = Q @ K^T * 0.125 -> fp16 ========= */
__global__ void __launch_bounds__(256)
score_k(const __half* __restrict__ qkv, __half* __restrict__ attn)
{
    __shared__ __half Qs[128 * 72];
    __shared__ __half Ks[128 * 72];

    const int tid = threadIdx.x, wid = tid >> 5, lane = tid & 31;
    const int lane4 = lane >> 2, lanek = lane & 3;
    const int warpM = wid & 1, warpN = wid >> 1;
    const int bh = blockIdx.z, b = bh / NHEAD, h = bh % NHEAD;
    const int m0 = blockIdx.y * 128, n0 = blockIdx.x * 128;

    const int mat = lane >> 3;
    const int arow = (lane & 7) + (mat & 1) * 8;
    const int acol = (mat >> 1) * 8;
    const int brow = lane & 7;
    const int bcol = ((lane >> 3) & 1) * 8;

    const __half* qb = qkv + (size_t)b * NTOK * QKVDIM + h * HDIM;
    const __half* kb = qb + CDIM;

    const uint4 zero4 = make_uint4(0, 0, 0, 0);
    #pragma unroll
    for (int p = 0; p < 2; p++) {
        int row = (tid >> 2) + p * 64;
        int col = (tid & 3) * 16;
        uint4 vq0 = zero4, vq1 = zero4, vk0 = zero4, vk1 = zero4;
        if (m0 + row < NTOK) {
            const __half* s = qb + (size_t)(m0 + row) * QKVDIM + col;
            vq0 = *(const uint4*)s; vq1 = *(const uint4*)(s + 8);
        }
        if (n0 + row < NTOK) {
            const __half* s = kb + (size_t)(n0 + row) * QKVDIM + col;
            vk0 = *(const uint4*)s; vk1 = *(const uint4*)(s + 8);
        }
        *(uint4*)&Qs[row * 72 + col]     = vq0;
        *(uint4*)&Qs[row * 72 + col + 8] = vq1;
        *(uint4*)&Ks[row * 72 + col]     = vk0;
        *(uint4*)&Ks[row * 72 + col + 8] = vk1;
    }
    __syncthreads();

    float acc[4][4][4];
    #pragma unroll
    for (int i = 0; i < 4; i++)
        #pragma unroll
        for (int j = 0; j < 4; j++)
            #pragma unroll
            for (int r = 0; r < 4; r++) acc[i][j][r] = 0.f;

    uint32_t aAddr[4], bAddr[4];
    const uint32_t qsb = smem_u32(Qs), ksb = smem_u32(Ks);
    #pragma unroll
    for (int mf = 0; mf < 4; mf++)
        aAddr[mf] = qsb + (uint32_t)(((warpM * 64 + mf * 16 + arow) * 72 + acol) * 2);
    #pragma unroll
    for (int nf = 0; nf < 4; nf++)
        bAddr[nf] = ksb + (uint32_t)(((warpN * 32 + nf * 8 + brow) * 72 + bcol) * 2);

    #pragma unroll
    for (int ks = 0; ks < 4; ks++) {
        uint32_t a[4][4], bb[4][2];
        #pragma unroll
        for (int mf = 0; mf < 4; mf++)
            ldsm_x4(a[mf][0], a[mf][1], a[mf][2], a[mf][3], aAddr[mf] + ks * 32);
        #pragma unroll
        for (int nf = 0; nf < 4; nf++)
            ldsm_x2(bb[nf][0], bb[nf][1], bAddr[nf] + ks * 32);
        #pragma unroll
        for (int mf = 0; mf < 4; mf++)
            #pragma unroll
            for (int nf = 0; nf < 4; nf++)
                mma_f16(acc[mf][nf][0], acc[mf][nf][1],
                        acc[mf][nf][2], acc[mf][nf][3],
                        a[mf][0], a[mf][1], a[mf][2], a[mf][3],
                        bb[nf][0], bb[nf][1]);
    }

    __half* ab = attn + (size_t)bh * ASTRIDE * ASTRIDE;
    #pragma unroll
    for (int mf = 0; mf < 4; mf++) {
        int m = m0 + warpM * 64 + mf * 16 + lane4;
        #pragma unroll
        for (int nf = 0; nf < 4; nf++) {
            int n = n0 + warpN * 32 + nf * 8 + lanek * 2;
            if (m < NTOK) {
                if (n + 1 < NTOK)
                    *(__half2*)(ab + (size_t)m * ASTRIDE + n) =
                        __floats2half2_rn(0.125f * acc[mf][nf][0], 0.125f * acc[mf][nf][1]);
                else if (n < NTOK)
                    ab[(size_t)m * ASTRIDE + n] = __float2half(0.125f * acc[mf][nf][0]);
            }
            if (m + 8 < NTOK) {
                if (n + 1 < NTOK)
                    *(__half2*)(ab + (size_t)(m + 8) * ASTRIDE + n) =
                        __floats2half2_rn(0.125f * acc[mf][nf][2], 0.125f * acc[mf][nf][3]);
                else if (n < NTOK)
                    ab[(size_t)(m + 8) * ASTRIDE + n] = __float2half(0.125f * acc[mf][nf][2]);
            }
        }
    }
}

/* ================= AV: O = P @ V (fp16 in/out) =========================== */
__global__ void __launch_bounds__(256)
av_k(const __half* __restrict__ attn, const __half* __restrict__ qkv,
     __half* __restrict__ ao)
{
    __shared__ __half As[128 * 40];
    __shared__ __half Vs[64 * 40];

    const int tid = threadIdx.x, wid = tid >> 5, lane = tid & 31;
    const int lane4 = lane >> 2, lanek = lane & 3;
    const int warpM = wid >> 1, warpN = wid & 1;
    const int bh = blockIdx.z, b = bh / NHEAD, h = bh % NHEAD;
    const int m0 = blockIdx.y * 128;

    const int mat = lane >> 3;
    const int arow = (lane & 7) + (mat & 1) * 8;
    const int acol = (mat >> 1) * 8;
    const int brow = lane & 7;
    const int bcol = ((lane >> 3) & 1) * 8;

    const __half* ab = attn + (size_t)bh * ASTRIDE * ASTRIDE;
    const __half* vb = qkv + (size_t)b * NTOK * QKVDIM + h * HDIM + 2 * CDIM;

    float acc[2][4][4];
    #pragma unroll
    for (int i = 0; i < 2; i++)
        #pragma unroll
        for (int j = 0; j < 4; j++)
            #pragma unroll
            for (int r = 0; r < 4; r++) acc[i][j][r] = 0.f;

    for (int t = 0; t < 7; t++) {
        const int k0 = t * 32;
        /* A tile 128x32 fp16 (rows guarded; pad cols are zero) */
        #pragma unroll
        for (int p = 0; p < 2; p++) {
            int row = (tid >> 2) + p * 64;
            int m = m0 + row;
            int c = (tid & 3) * 8;
            uint4 u = make_uint4(0, 0, 0, 0);
            if (m < NTOK) u = *(const uint4*)(ab + (size_t)m * ASTRIDE + k0 + c);
            *(uint4*)&As[row * 40 + c] = u;
        }
        /* V tile 32k x 64n transposed into Vs[n][kk] */
        {
            int n = tid & 63;
            #pragma unroll
            for (int i = 0; i < 8; i++) {
                int kk = (tid >> 6) + 4 * i;
                int kg = k0 + kk;
                __half v = (kg < NTOK) ? vb[(size_t)kg * QKVDIM + n] : __half(0.f);
                Vs[n * 40 + kk] = v;
            }
        }
        __syncthreads();

        uint32_t aAddr[2], bAddr[4];
        const uint32_t asb2 = smem_u32(As), vsb = smem_u32(Vs);
        #pragma unroll
        for (int mf = 0; mf < 2; mf++)
            aAddr[mf] = asb2 + (uint32_t)(((warpM * 32 + mf * 16 + arow) * 40 + acol) * 2);
        #pragma unroll
        for (int nf = 0; nf < 4; nf++)
            bAddr[nf] = vsb + (uint32_t)(((warpN * 32 + nf * 8 + brow) * 40 + bcol) * 2);

        #pragma unroll
        for (int ks = 0; ks < 2; ks++) {
            uint32_t a[2][4], bb[4][2];
            #pragma unroll
            for (int mf = 0; mf < 2; mf++)
                ldsm_x4(a[mf][0], a[mf][1], a[mf][2], a[mf][3], aAddr[mf] + ks * 32);
            #pragma unroll
            for (int nf = 0; nf < 4; nf++)
                ldsm_x2(bb[nf][0], bb[nf][1], bAddr[nf] + ks * 32);
            #pragma unroll
            for (int mf = 0; mf < 2; mf++)
                #pragma unroll
                for (int nf = 0; nf < 4; nf++)
                    mma_f16(acc[mf][nf][0], acc[mf][nf][1],
                            acc[mf][nf][2], acc[mf][nf][3],
                            a[mf][0], a[mf][1], a[mf][2], a[mf][3],
                            bb[nf][0], bb[nf][1]);
        }
        __syncthreads();
    }

    #pragma unroll
    for (int mf = 0; mf < 2; mf++) {
        int m = m0 + warpM * 32 + mf * 16 + lane4;
        #pragma unroll
        for (int nf = 0; nf < 4; nf++) {
            int n = warpN * 32 + nf * 8 + lanek * 2;
            if (m < NTOK)
                *(__half2*)(ao + (size_t)(b * NTOK + m) * CDIM + h * HDIM + n) =
                    __floats2half2_rn(acc[mf][nf][0], acc[mf][nf][1]);
            if (m + 8 < NTOK)
                *(__half2*)(ao + (size_t)(b * NTOK + m + 8) * CDIM + h * HDIM + n) =
                    __floats2half2_rn(acc[mf][nf][2], acc[mf][nf][3]);
        }
    }
}

/* ---------------- block reductions --------------------------------------- */
__device__ __forceinline__ float blockReduceSum(float v, float* sh) {
    int tid = threadIdx.x, lane = tid & 31, w = tid >> 5;
    #pragma unroll
    for (int o = 16; o; o >>= 1) v += __shfl_xor_sync(0xffffffffu, v, o);
    if (lane == 0) sh[w] = v;
    __syncthreads();
    int nw = (blockDim.x + 31) >> 5;
    v = (tid < nw) ? sh[tid] : 0.f;
    if (w == 0) {
        #pragma unroll
        for (int o = 16; o; o >>= 1) v += __shfl_xor_sync(0xffffffffu, v, o);
        if (lane == 0) sh[0] = v;
    }
    __syncthreads();
    float r = sh[0];
    __syncthreads();
    return r;
}

/* ---------------- warp-per-row policy softmax (fp16 rows) ----------------- */
__global__ void __launch_bounds__(256)
softmax_pol_k(__half* __restrict__ attn, const float* __restrict__ pol)
{
    int wid = threadIdx.x >> 5, lane = threadIdx.x & 31;
    long long r = (long long)blockIdx.x * 8 + wid;
    int bh = (int)(r / NTOK), n = (int)(r % NTOK);
    int b = bh / NHEAD;
    __half* row = attn + ((size_t)bh * ASTRIDE + n) * ASTRIDE;
    const float* pb = pol + b * NTOK;

    float v[7];
    float mx = -1e30f;
    #pragma unroll
    for (int i = 0; i < 7; i++) {
        int m = lane + 32 * i;
        v[i] = (m < NTOK) ? __half2float(row[m]) : -1e30f;
        mx = fmaxf(mx, v[i]);
    }
    #pragma unroll
    for (int o = 16; o; o >>= 1) mx = fmaxf(mx, __shfl_xor_sync(0xffffffffu, mx, o));

    float sum = 0.f;
    #pragma unroll
    for (int i = 0; i < 7; i++) {
        int m = lane + 32 * i;
        if (m < NTOK) {
            float ap = (m == n) ? 1.0f : pb[m];
            float e = expf(v[i] - mx) * ap;
            v[i] = e;
            sum += e;
        }
    }
    #pragma unroll
    for (int o = 16; o; o >>= 1) sum += __shfl_xor_sync(0xffffffffu, sum, o);
    float inv = 1.0f / sum;
    #pragma unroll
    for (int i = 0; i < 7; i++) {
        int m = lane + 32 * i;
        if (m < NTOK) row[m] = __float2half(v[i] * inv);
    }
}

/* ---------------- LayerNorm over C=384 -> fp16 out ------------------------ */
__global__ void ln_k(const float* __restrict__ x, const float* __restrict__ w,
                     const float* __restrict__ bb, __half* __restrict__ out, float eps)
{
    __shared__ float sh[32];
    long long row = blockIdx.x;
    const float* xr = x + row * CDIM;
    int tid = threadIdx.x; /* 128 */
    float v0 = xr[tid], v1 = xr[tid + 128], v2 = xr[tid + 256];
    float s = blockReduceSum(v0 + v1 + v2, sh);
    float m = s * (1.f / 384.f);
    float d0 = v0 - m, d1 = v1 - m, d2 = v2 - m;
    float q = blockReduceSum(d0*d0 + d1*d1 + d2*d2, sh);
    float rs = rsqrtf(q * (1.f / 384.f) + eps);
    __half* orow = out + row * CDIM;
    orow[tid]       = __float2half(d0 * rs * w[tid]       + bb[tid]);
    orow[tid + 128] = __float2half(d1 * rs * w[tid + 128] + bb[tid + 128]);
    orow[tid + 256] = __float2half(d2 * rs * w[tid + 256] + bb[tid + 256]);
}

/* ---------------- init / final ------------------------------------------- */
__global__ void init_x_k(const float* __restrict__ xin, const float* __restrict__ cls,
                         const float* __restrict__ polin,
                         float* __restrict__ x, float* __restrict__ pol)
{
    long long idx = (long long)blockIdx.x * blockDim.x + threadIdx.x;
    long long total = (long long)MROWS * CDIM;
    if (idx < total) {
        int c  = (int)(idx % CDIM);
        int nn = (int)((idx / CDIM) % NTOK);
        int b  = (int)(idx / ((long long)CDIM * NTOK));
        float v;
        if (nn == 0) v = cls[b * CDIM + c];
        else         v = xin[((long long)b * CDIM + c) * NSP + (nn - 1)];
        x[idx] = v;
    }
    if (idx < BATCH * NTOK) pol[idx] = polin[idx];
}

__global__ void final_k(const float* __restrict__ x, float* __restrict__ out)
{
    long long idx = (long long)blockIdx.x * blockDim.x + threadIdx.x;
    const long long total_sp = (long long)BATCH * CDIM * NSP;
    if (idx < total_sp) {
        int hw = (int)(idx % NSP);
        int c  = (int)((idx / NSP) % CDIM);
        int b  = (int)(idx / ((long long)NSP * CDIM));
        out[idx] = x[((long long)(b * NTOK) + 1 + hw) * CDIM + c];
    } else if (idx < total_sp + (long long)BATCH * CDIM) {
        long long rr = idx - total_sp;
        int c = (int)(rr % CDIM);
        int b = (int)(rr / CDIM);
        out[idx] = x[((long long)b * NTOK) * CDIM + c];
    }
}

/* ---------------- predictor --------------------------------------------- */
__global__ void den_k(const float* __restrict__ pol, float* __restrict__ den)
{
    __shared__ float sh[32];
    int b = blockIdx.x;
    int tid = threadIdx.x;
    float v = (tid < NSP) ? pol[b * NTOK + 1 + tid] : 0.f;
    float s = blockReduceSum(v, sh);
    if (tid == 0) den[b] = s;
}

__global__ void p1_k(const float* __restrict__ x,
                     const float* __restrict__ lnw, const float* __restrict__ lnb,
                     const float* __restrict__ Win, const float* __restrict__ bin,
                     float* __restrict__ ph)
{
    int bn = blockIdx.x;
    int b = bn / NSP, n = bn % NSP;
    int wid = threadIdx.x >> 5, lane = threadIdx.x & 31;
    __shared__ float sh[NHEAD][HDIM];

    const float* xr = x + ((long long)(b * NTOK + 1 + n)) * CDIM + wid * HDIM;
    float v0 = xr[lane], v1 = xr[lane + 32];
    float s = v0 + v1;
    #pragma unroll
    for (int o = 16; o; o >>= 1) s += __shfl_xor_sync(0xffffffffu, s, o);
    float m = s * (1.f / 64.f);
    float d0 = v0 - m, d1 = v1 - m;
    float q = d0*d0 + d1*d1;
    #pragma unroll
    for (int o = 16; o; o >>= 1) q += __shfl_xor_sync(0xffffffffu, q, o);
    float rs = rsqrtf(q * (1.f / 64.f) + 1e-5f);
    sh[wid][lane]      = d0 * rs * lnw[lane]      + lnb[lane];
    sh[wid][lane + 32] = d1 * rs * lnw[lane + 32] + lnb[lane + 32];
    __syncwarp();

    float a0 = bin[lane], a1 = bin[lane + 32];
    const float* w0 = Win + lane * 64;
    const float* w1 = Win + (lane + 32) * 64;
    #pragma unroll 8
    for (int e = 0; e < 64; e++) {
        float he = sh[wid][e];
        a0 += w0[e] * he;
        a1 += w1[e] * he;
    }
    float* o = ph + ((long long)bn * NHEAD + wid) * HDIM;
    o[lane]      = gelu_f(a0);
    o[lane + 32] = gelu_f(a1);
}

__global__ void p2_k(const float* __restrict__ ph, const float* __restrict__ pol,
                     const float* __restrict__ den, float* __restrict__ glob)
{
    int bh = blockIdx.x;
    int b = bh / NHEAD, h = bh % NHEAD;
    int tid = threadIdx.x;
    int d = tid & 31, seg = tid >> 5;
    float s = 0.f;
    for (int n = seg; n < NSP; n += 8)
        s += ph[(((long long)(b * NSP + n)) * NHEAD + h) * HDIM + 32 + d]
             * pol[b * NTOK + 1 + n];
    __shared__ float sh[8][32];
    sh[seg][d] = s;
    __syncthreads();
    if (seg == 0) {
        float t = 0.f;
        #pragma unroll
        for (int k = 0; k < 8; k++) t += sh[k][d];
        glob[(b * NHEAD + h) * 32 + d] = t / den[b];
    }
}

__global__ void p3_k(const float* __restrict__ ph, const float* __restrict__ glob,
                     const float* __restrict__ W1, const float* __restrict__ b1,
                     const float* __restrict__ W2, const float* __restrict__ b2,
                     const float* __restrict__ W3, const float* __restrict__ b3,
                     const float* __restrict__ gum, float* __restrict__ pol)
{
    int bn = blockIdx.x;
    int b = bn / NSP, n = bn % NSP;
    int wid = threadIdx.x >> 5, lane = threadIdx.x & 31;
    __shared__ float h2[NHEAD][64];
    __shared__ float o1[NHEAD][32];
    __shared__ float o2[NHEAD][16];
    __shared__ float zz[NHEAD][2];

    const float* hin = ph + ((long long)bn * NHEAD + wid) * HDIM;
    h2[wid][lane]      = hin[lane];
    h2[wid][32 + lane] = glob[(b * NHEAD + wid) * 32 + lane];
    __syncwarp();
    {
        float a = b1[lane];
        const float* wr = W1 + lane * 64;
        #pragma unroll 8
        for (int e = 0; e < 64; e++) a += wr[e] * h2[wid][e];
        o1[wid][lane] = gelu_f(a);
    }
    __syncwarp();
    if (lane < 16) {
        float a = b2[lane];
        const float* wr = W2 + lane * 32;
        #pragma unroll 8
        for (int e = 0; e < 32; e++) a += wr[e] * o1[wid][e];
        o2[wid][lane] = gelu_f(a);
    }
    __syncwarp();
    if (lane < 2) {
        float a = b3[lane];
        const float* wr = W3 + lane * 16;
        #pragma unroll
        for (int e = 0; e < 16; e++) a += wr[e] * o2[wid][e];
        zz[wid][lane] = a;
    }
    __syncthreads();
    if (threadIdx.x == 0) {
        float s0 = 0.f, s1 = 0.f;
        #pragma unroll
        for (int h = 0; h < NHEAD; h++) {
            float z0 = zz[h][0], z1 = zz[h][1];
            float mx = fmaxf(z0, z1);
            float lse = mx + logf(expf(z0 - mx) + expf(z1 - mx));
            s0 += z0 - lse;
            s1 += z1 - lse;
        }
        s0 *= (1.f / 6.f); s1 *= (1.f / 6.f);
        float u0 = gum[((long long)b * NSP + n) * 2 + 0];
        float u1 = gum[((long long)b * NSP + n) * 2 + 1];
        float g0 = -logf(-logf(u0 + 1e-10f) + 1e-10f);
        float g1 = -logf(-logf(u1 + 1e-10f) + 1e-10f);
        int idx = b * NTOK + 1 + n;
        float keep = (s0 + g0 >= s1 + g1) ? pol[idx] : 0.f;
        pol[idx] = keep;
    }
}

/* ---------------- host-side ------------------------------------------------ */
extern "C" void kernel_launch(void* const* d_in, const int* in_sizes, int n_in,
                              void* d_out, int out_size)
{
    const float* in_x     = (const float*)d_in[0];
    const float* in_cls   = (const float*)d_in[1];
    const float* in_pol   = (const float*)d_in[2];
    const float* in_gum   = (const float*)d_in[3];
    const float* ln1_w    = (const float*)d_in[4];
    const float* ln1_b    = (const float*)d_in[5];
    const float* qkv_w    = (const float*)d_in[6];
    const float* qkv_b    = (const float*)d_in[7];
    const float* proj_w   = (const float*)d_in[8];
    const float* proj_b   = (const float*)d_in[9];
    const float* ln2_w    = (const float*)d_in[10];
    const float* ln2_b    = (const float*)d_in[11];
    const float* fc1_w    = (const float*)d_in[12];
    const float* fc1_b    = (const float*)d_in[13];
    const float* fc2_w    = (const float*)d_in[14];
    const float* fc2_b    = (const float*)d_in[15];
    const float* p_ln_w   = (const float*)d_in[16];
    const float* p_ln_b   = (const float*)d_in[17];
    const float* p_in_w   = (const float*)d_in[18];
    const float* p_in_b   = (const float*)d_in[19];
    const float* p_o1_w   = (const float*)d_in[20];
    const float* p_o1_b   = (const float*)d_in[21];
    const float* p_o2_w   = (const float*)d_in[22];
    const float* p_o2_b   = (const float*)d_in[23];
    const float* p_o3_w   = (const float*)d_in[24];
    const float* p_o3_b   = (const float*)d_in[25];

    cudaFuncSetAttribute(hgemm_k<0, true >, cudaFuncAttributeMaxDynamicSharedMemorySize, DENSE_SMEM);
    cudaFuncSetAttribute(hgemm_k<1, true >, cudaFuncAttributeMaxDynamicSharedMemorySize, DENSE_SMEM);
    cudaFuncSetAttribute(hgemm_k<2, false>, cudaFuncAttributeMaxDynamicSharedMemorySize, DENSE_SMEM);

    float  *px, *ppol, *pph, *pglob, *pden;
    __half *pattn, *ph16, *pqkv16, *pao16, *pffn16, *pwh;
    cudaGetSymbolAddress((void**)&px,     g_x);
    cudaGetSymbolAddress((void**)&pattn,  g_attn);
    cudaGetSymbolAddress((void**)&ph16,   g_h16);
    cudaGetSymbolAddress((void**)&pqkv16, g_qkv16);
    cudaGetSymbolAddress((void**)&pao16,  g_ao16);
    cudaGetSymbolAddress((void**)&pffn16, g_ffn16);
    cudaGetSymbolAddress((void**)&pwh,    g_wh);
    cudaGetSymbolAddress((void**)&ppol,   g_pol);
    cudaGetSymbolAddress((void**)&pph,    g_ph);
    cudaGetSymbolAddress((void**)&pglob,  g_glob);
    cudaGetSymbolAddress((void**)&pden,   g_den);

    /* weights fp32 -> fp16 scratch (per-layer packed) */
    {
        long long nq = (long long)DEPTHN * QKVDIM * CDIM;
        long long np = (long long)DEPTHN * CDIM * CDIM;
        long long n1 = (long long)DEPTHN * FFDIM * CDIM;
        long long n2 = (long long)DEPTHN * CDIM * FFDIM;
        cvtw_k<<<(int)((nq + 255) / 256), 256>>>(qkv_w,  pwh, QKVDIM * CDIM, W_QKV_OFF,  nq);
        cvtw_k<<<(int)((np + 255) / 256), 256>>>(proj_w, pwh, CDIM * CDIM,   W_PROJ_OFF, np);
        cvtw_k<<<(int)((n1 + 255) / 256), 256>>>(fc1_w,  pwh, FFDIM * CDIM,  W_FC1_OFF,  n1);
        cvtw_k<<<(int)((n2 + 255) / 256), 256>>>(fc2_w,  pwh, CDIM * FFDIM,  W_FC2_OFF,  n2);
    }

    {
        long long total = (long long)MROWS * CDIM;
        int blocks = (int)((total + 255) / 256);
        init_x_k<<<blocks, 256>>>(in_x, in_cls, in_pol, px, ppol);
    }

    int pc = 0;
    for (int i = 0; i < DEPTHN; i++) {
        const __half* wl = pwh + (long long)i * LW;
        if (i == 3 || i == 6 || i == 9) {
            den_k<<<BATCH, 256>>>(ppol, pden);
            p1_k<<<BATCH * NSP, 192>>>(px,
                p_ln_w + pc * HDIM, p_ln_b + pc * HDIM,
                p_in_w + pc * HDIM * HDIM, p_in_b + pc * HDIM, pph);
            p2_k<<<BATCH * NHEAD, 256>>>(pph, ppol, pden, pglob);
            p3_k<<<BATCH * NSP, 192>>>(pph, pglob,
                p_o1_w + pc * 32 * 64, p_o1_b + pc * 32,
                p_o2_w + pc * 16 * 32, p_o2_b + pc * 16,
                p_o3_w + pc * 2 * 16,  p_o3_b + pc * 2,
                in_gum + (long long)pc * BATCH * NSP * 2, ppol);
            pc++;
        }

        ln_k<<<MROWS, 128>>>(px, ln1_w + i * CDIM, ln1_b + i * CDIM, ph16, 1e-6f);

        hgemm_k<0, true><<<dim3(QKVDIM / 128, MROWS / 128), 256, DENSE_SMEM>>>(
            ph16, wl + W_QKV_OFF, qkv_b + i * QKVDIM, nullptr, pqkv16,
            CDIM, CDIM, CDIM, QKVDIM);

        score_k<<<dim3(2, 2, BATCH * NHEAD), 256>>>(pqkv16, pattn);

        softmax_pol_k<<<(BATCH * NHEAD * NTOK) / 8, 256>>>(pattn, ppol);

        av_k<<<dim3(1, 2, BATCH * NHEAD), 256>>>(pattn, pqkv16, pao16);

        hgemm_k<2, false><<<dim3(CDIM / 128, MROWS / 128), 256, DENSE_SMEM>>>(
            pao16, wl + W_PROJ_OFF, proj_b + i * CDIM, px, px,
            CDIM, CDIM, CDIM, CDIM);

        ln_k<<<MROWS, 128>>>(px, ln2_w + i * CDIM, ln2_b + i * CDIM, ph16, 1e-6f);

        hgemm_k<1, true><<<dim3(FFDIM / 128, MROWS / 128), 256, DENSE_SMEM>>>(
            ph16, wl + W_FC1_OFF, fc1_b + i * FFDIM, nullptr, pffn16,
            CDIM, CDIM, CDIM, FFDIM);

        hgemm_k<2, false><<<dim3(CDIM / 128, MROWS / 128), 256, DENSE_SMEM>>>(
            pffn16, wl + W_FC2_OFF, fc2_b + i * CDIM, px, px,
            FFDIM, FFDIM, FFDIM, CDIM);
    }

    {
        long long total = (long long)BATCH * CDIM * NSP + (long long)BATCH * CDIM;
        int blocks = (int)((total + 255) / 256);
        final_k<<<blocks, 256>>>(px, (float*)d_out);
    }
}